// round 2
// baseline (speedup 1.0000x reference)
#include <cuda_runtime.h>
#include <math.h>

#define NTOK 64
#define DIM 128
#define NHEADS 4
#define HDIM 32
#define XPAD 132      // 64x128 tiles padded: 132 % 32 = 4 -> conflict-free row strides
#define KTPAD 68      // transposed K [128][64] padded
#define SPAD 68       // scores [64][64] padded

// [h][i][j] expanded dynamic position bias (tiny; L2-resident)
__device__ float g_bias[NHEADS * NTOK * NTOK];

// ---------------------------------------------------------------------------
// Kernel 1: CPB MLP -> bias table -> expand via rel_index (trivial cost)
// ---------------------------------------------------------------------------
__global__ void cpb_kernel(const float* __restrict__ cpb_w1,
                           const float* __restrict__ cpb_b1,
                           const float* __restrict__ cpb_w2,
                           const float* __restrict__ h_times,
                           const float* __restrict__ pow_para,
                           const float* __restrict__ ws1,
                           const float* __restrict__ ws2,
                           const int*   __restrict__ rel_index,
                           const float* __restrict__ coords)
{
    __shared__ float table[225 * 4];
    int t = threadIdx.x;
    if (t < 225) {
        float ht = log1pf(expf(h_times[0]));                    // softplus
        float pp = 1.0f / (1.0f + expf(-pow_para[0]));          // sigmoid
        float ws = log1pf(expf(ws1[0])) / log1pf(expf(ws2[0]));
        float t0 = coords[t * 2 + 0] * ht;
        float t1 = coords[t * 2 + 1] * ht;
        // jnp.sign semantics: sign(0) = 0
        float s0 = (float)((t0 > 0.f) - (t0 < 0.f));
        float s1 = (float)((t1 > 0.f) - (t1 < 0.f));
        t0 = s0 * powf(fabsf(t0) + 1e-6f, pp) * ws;
        t1 = s1 * powf(fabsf(t1) + 1e-6f, pp) * ws;
        float a0 = 0.f, a1 = 0.f, a2 = 0.f, a3 = 0.f;
        for (int j = 0; j < 512; j++) {
            float hsum = fmaf(t0, cpb_w1[j], fmaf(t1, cpb_w1[512 + j], cpb_b1[j]));
            hsum = fmaxf(hsum, 0.f);
            a0 = fmaf(hsum, cpb_w2[j * 4 + 0], a0);
            a1 = fmaf(hsum, cpb_w2[j * 4 + 1], a1);
            a2 = fmaf(hsum, cpb_w2[j * 4 + 2], a2);
            a3 = fmaf(hsum, cpb_w2[j * 4 + 3], a3);
        }
        table[t * 4 + 0] = a0; table[t * 4 + 1] = a1;
        table[t * 4 + 2] = a2; table[t * 4 + 3] = a3;
    }
    __syncthreads();
    for (int i = t; i < NHEADS * NTOK * NTOK; i += blockDim.x) {
        int h  = i / (NTOK * NTOK);
        int ij = i % (NTOK * NTOK);
        g_bias[i] = table[rel_index[ij] * 4 + h];
    }
}

// ---------------------------------------------------------------------------
// Kernel 2: fused window attention, one block per window, 256 threads
// ---------------------------------------------------------------------------
__global__ void __launch_bounds__(256)
attn_kernel(const float* __restrict__ x,
            const float* __restrict__ Wqkv,
            const float* __restrict__ Wproj,
            const float* __restrict__ bproj,
            float*       __restrict__ out)
{
    extern __shared__ float sm[];
    float* xs = sm;                        // [64][132] x, later reused as O
    float* Qs = xs + NTOK * XPAD;          // [64][132] (scaled q)
    float* Kt = Qs + NTOK * XPAD;          // [128][68] K transposed: [channel][token]
    float* Vs = Kt + DIM * KTPAD;          // [64][132]
    float* Ss = Vs + NTOK * XPAD;          // [64][68] scores/probs
    float* Ws = Ss + NTOK * SPAD;          // [32][128] staged weight chunk

    const int tid = threadIdx.x;
    const int ty = tid >> 4, tx = tid & 15;   // 16 x 16 thread grid
    const int b = blockIdx.x;

    // ---- load x tile (coalesced float4) ----
    const float4* xb = (const float4*)(x + (size_t)b * NTOK * DIM);
    #pragma unroll
    for (int i = tid; i < NTOK * DIM / 4; i += 256) {
        float4 v = xb[i];
        int r = i >> 5, c = (i & 31) << 2;
        float* p = xs + r * XPAD + c;
        p[0] = v.x; p[1] = v.y; p[2] = v.z; p[3] = v.w;
    }

    const float scale = 0.1767766952966369f;   // 32^-0.5

    // ---- Phase B: qkv = x @ Wqkv, three 64x128 panels (q, k, v) ----
    for (int p = 0; p < 3; p++) {
        float acc[4][8];
        #pragma unroll
        for (int i = 0; i < 4; i++)
            #pragma unroll
            for (int j = 0; j < 8; j++) acc[i][j] = 0.f;

        for (int k0 = 0; k0 < DIM; k0 += 32) {
            __syncthreads();   // also covers x-load completion on first pass
            const float* wsrc = Wqkv + (size_t)k0 * 384 + p * DIM;
            for (int i = tid; i < 32 * DIM / 4; i += 256) {
                int kk = i >> 5, c = (i & 31) << 2;
                *(float4*)(Ws + kk * DIM + c) =
                    *(const float4*)(wsrc + (size_t)kk * 384 + c);
            }
            __syncthreads();
            #pragma unroll 8
            for (int kk = 0; kk < 32; kk++) {
                float a[4];
                #pragma unroll
                for (int i = 0; i < 4; i++)
                    a[i] = xs[(ty * 4 + i) * XPAD + k0 + kk];
                float4 w0 = *(const float4*)(Ws + kk * DIM + tx * 4);
                float4 w1 = *(const float4*)(Ws + kk * DIM + 64 + tx * 4);
                float w[8] = {w0.x, w0.y, w0.z, w0.w, w1.x, w1.y, w1.z, w1.w};
                #pragma unroll
                for (int i = 0; i < 4; i++)
                    #pragma unroll
                    for (int j = 0; j < 8; j++)
                        acc[i][j] = fmaf(a[i], w[j], acc[i][j]);
            }
        }
        // write panel result
        if (p == 1) {
            // K stored transposed: Kt[channel][token]
            #pragma unroll
            for (int i = 0; i < 4; i++) {
                int r = ty * 4 + i;
                #pragma unroll
                for (int j = 0; j < 4; j++) {
                    Kt[(tx * 4 + j) * KTPAD + r]      = acc[i][j];
                    Kt[(64 + tx * 4 + j) * KTPAD + r] = acc[i][4 + j];
                }
            }
        } else {
            float* dst = (p == 0) ? Qs : Vs;
            float mul = (p == 0) ? scale : 1.0f;
            #pragma unroll
            for (int i = 0; i < 4; i++) {
                int r = ty * 4 + i;
                float4 v0 = make_float4(acc[i][0]*mul, acc[i][1]*mul, acc[i][2]*mul, acc[i][3]*mul);
                float4 v1 = make_float4(acc[i][4]*mul, acc[i][5]*mul, acc[i][6]*mul, acc[i][7]*mul);
                *(float4*)(dst + r * XPAD + tx * 4)      = v0;
                *(float4*)(dst + r * XPAD + 64 + tx * 4) = v1;
            }
        }
    }
    __syncthreads();

    // ---- Phase C/D per head: S = Q Kt + bias, softmax, O = S V ----
    for (int h = 0; h < NHEADS; h++) {
        float acc[4][4];
        #pragma unroll
        for (int i = 0; i < 4; i++)
            #pragma unroll
            for (int j = 0; j < 4; j++) acc[i][j] = 0.f;

        const float* Qh  = Qs + h * HDIM;
        const float* Kth = Kt + h * HDIM * KTPAD;
        #pragma unroll 8
        for (int kk = 0; kk < HDIM; kk++) {
            float4 kv = *(const float4*)(Kth + kk * KTPAD + tx * 4);
            float q[4];
            #pragma unroll
            for (int i = 0; i < 4; i++)
                q[i] = Qh[(ty * 4 + i) * XPAD + kk];
            #pragma unroll
            for (int i = 0; i < 4; i++) {
                acc[i][0] = fmaf(q[i], kv.x, acc[i][0]);
                acc[i][1] = fmaf(q[i], kv.y, acc[i][1]);
                acc[i][2] = fmaf(q[i], kv.z, acc[i][2]);
                acc[i][3] = fmaf(q[i], kv.w, acc[i][3]);
            }
        }
        // add bias, write scores
        const float* bh = g_bias + h * NTOK * NTOK;
        #pragma unroll
        for (int i = 0; i < 4; i++) {
            int r = ty * 4 + i;
            float4 bv = *(const float4*)(bh + r * 64 + tx * 4);
            float* srow = Ss + r * SPAD + tx * 4;
            srow[0] = acc[i][0] + bv.x;
            srow[1] = acc[i][1] + bv.y;
            srow[2] = acc[i][2] + bv.z;
            srow[3] = acc[i][3] + bv.w;
        }
        __syncthreads();

        // softmax: 4 threads (a warp quad) per row
        {
            int row = tid >> 2, seg = tid & 3;
            float* sr = Ss + row * SPAD + seg * 16;
            float vals[16];
            float mx = -1e30f;
            #pragma unroll
            for (int j = 0; j < 16; j++) { vals[j] = sr[j]; mx = fmaxf(mx, vals[j]); }
            mx = fmaxf(mx, __shfl_xor_sync(0xffffffffu, mx, 1));
            mx = fmaxf(mx, __shfl_xor_sync(0xffffffffu, mx, 2));
            float sum = 0.f;
            #pragma unroll
            for (int j = 0; j < 16; j++) { vals[j] = __expf(vals[j] - mx); sum += vals[j]; }
            sum += __shfl_xor_sync(0xffffffffu, sum, 1);
            sum += __shfl_xor_sync(0xffffffffu, sum, 2);
            float inv = 1.0f / sum;
            #pragma unroll
            for (int j = 0; j < 16; j++) sr[j] = vals[j] * inv;
        }
        __syncthreads();

        // O_h = S @ V_h  (64x32), thread: 4 rows x 2 cols; O recycled into xs
        float oacc[4][2];
        #pragma unroll
        for (int i = 0; i < 4; i++) { oacc[i][0] = 0.f; oacc[i][1] = 0.f; }
        #pragma unroll 8
        for (int m = 0; m < NTOK; m++) {
            float2 vv = *(const float2*)(Vs + m * XPAD + h * HDIM + tx * 2);
            float s[4];
            #pragma unroll
            for (int i = 0; i < 4; i++)
                s[i] = Ss[(ty * 4 + i) * SPAD + m];
            #pragma unroll
            for (int i = 0; i < 4; i++) {
                oacc[i][0] = fmaf(s[i], vv.x, oacc[i][0]);
                oacc[i][1] = fmaf(s[i], vv.y, oacc[i][1]);
            }
        }
        #pragma unroll
        for (int i = 0; i < 4; i++) {
            *(float2*)(xs + (ty * 4 + i) * XPAD + h * HDIM + tx * 2) =
                make_float2(oacc[i][0], oacc[i][1]);
        }
        __syncthreads();
    }

    // ---- Phase E: Y = O @ Wproj + bproj ----
    {
        float acc[4][8];
        #pragma unroll
        for (int i = 0; i < 4; i++)
            #pragma unroll
            for (int j = 0; j < 8; j++) acc[i][j] = 0.f;

        for (int k0 = 0; k0 < DIM; k0 += 32) {
            __syncthreads();
            const float* wsrc = Wproj + (size_t)k0 * DIM;
            for (int i = tid; i < 32 * DIM / 4; i += 256) {
                int kk = i >> 5, c = (i & 31) << 2;
                *(float4*)(Ws + kk * DIM + c) =
                    *(const float4*)(wsrc + (size_t)kk * DIM + c);
            }
            __syncthreads();
            #pragma unroll 8
            for (int kk = 0; kk < 32; kk++) {
                float a[4];
                #pragma unroll
                for (int i = 0; i < 4; i++)
                    a[i] = xs[(ty * 4 + i) * XPAD + k0 + kk];
                float4 w0 = *(const float4*)(Ws + kk * DIM + tx * 4);
                float4 w1 = *(const float4*)(Ws + kk * DIM + 64 + tx * 4);
                float w[8] = {w0.x, w0.y, w0.z, w0.w, w1.x, w1.y, w1.z, w1.w};
                #pragma unroll
                for (int i = 0; i < 4; i++)
                    #pragma unroll
                    for (int j = 0; j < 8; j++)
                        acc[i][j] = fmaf(a[i], w[j], acc[i][j]);
            }
        }

        float* ob = out + (size_t)b * NTOK * DIM;
        float4 bb0 = *(const float4*)(bproj + tx * 4);
        float4 bb1 = *(const float4*)(bproj + 64 + tx * 4);
        #pragma unroll
        for (int i = 0; i < 4; i++) {
            int r = ty * 4 + i;
            float4 r0 = make_float4(acc[i][0] + bb0.x, acc[i][1] + bb0.y,
                                    acc[i][2] + bb0.z, acc[i][3] + bb0.w);
            float4 r1 = make_float4(acc[i][4] + bb1.x, acc[i][5] + bb1.y,
                                    acc[i][6] + bb1.z, acc[i][7] + bb1.w);
            *(float4*)(ob + r * DIM + tx * 4)      = r0;
            *(float4*)(ob + r * DIM + 64 + tx * 4) = r1;
        }
    }
}

// ---------------------------------------------------------------------------
// Launch
// ---------------------------------------------------------------------------
extern "C" void kernel_launch(void* const* d_in, const int* in_sizes, int n_in,
                              void* d_out, int out_size)
{
    const float* x        = (const float*)d_in[0];
    const float* Wqkv     = (const float*)d_in[1];
    const float* Wproj    = (const float*)d_in[2];
    const float* bproj    = (const float*)d_in[3];
    const float* cpb_w1   = (const float*)d_in[4];
    const float* cpb_b1   = (const float*)d_in[5];
    const float* cpb_w2   = (const float*)d_in[6];
    const float* h_times  = (const float*)d_in[7];
    const float* pow_para = (const float*)d_in[8];
    const float* ws1      = (const float*)d_in[9];
    const float* ws2      = (const float*)d_in[10];
    const int*   rel_idx  = (const int*)d_in[11];
    const float* coords   = (const float*)d_in[12];

    int nwin = in_sizes[0] / (NTOK * DIM);

    int smem_floats = NTOK * XPAD      // xs / O
                    + NTOK * XPAD      // Qs
                    + DIM * KTPAD      // Kt
                    + NTOK * XPAD      // Vs
                    + NTOK * SPAD      // Ss
                    + 32 * DIM;        // Ws
    int smem_bytes = smem_floats * (int)sizeof(float);

    cudaFuncSetAttribute(attn_kernel,
                         cudaFuncAttributeMaxDynamicSharedMemorySize, smem_bytes);

    cpb_kernel<<<1, 256>>>(cpb_w1, cpb_b1, cpb_w2, h_times, pow_para,
                           ws1, ws2, rel_idx, coords);
    attn_kernel<<<nwin, 256, smem_bytes>>>(x, Wqkv, Wproj, bproj, (float*)d_out);
}

// round 3
// speedup vs baseline: 1.6406x; 1.6406x over previous
#include <cuda_runtime.h>
#include <math.h>

#define NTOK 64
#define DIM 128
#define NHEADS 4
#define SCALE 0.1767766952966369f   // 32^-0.5

// smem strides (floats)
#define XS 132    // xs / qs / vs row stride
#define KTS 68    // kT row stride (kT[channel][token])
#define SS 68     // scores row stride
#define WBS 388   // Wqkv staging stride

__device__ float g_bias[NHEADS * NTOK * NTOK];

__device__ __forceinline__ unsigned f2tf(float x) {
    unsigned r; asm("cvt.rna.tf32.f32 %0, %1;" : "=r"(r) : "f"(x)); return r;
}
__device__ __forceinline__ float uaf(unsigned x) { return __uint_as_float(x); }
__device__ __forceinline__ unsigned fau(float x) { return __float_as_uint(x); }

__device__ __forceinline__ void mma8(float* c, const unsigned* a, const unsigned* b) {
    asm volatile(
        "mma.sync.aligned.m16n8k8.row.col.f32.tf32.tf32.f32 "
        "{%0,%1,%2,%3}, {%4,%5,%6,%7}, {%8,%9}, {%0,%1,%2,%3};"
        : "+f"(c[0]), "+f"(c[1]), "+f"(c[2]), "+f"(c[3])
        : "r"(a[0]), "r"(a[1]), "r"(a[2]), "r"(a[3]), "r"(b[0]), "r"(b[1]));
}

// ---------------------------------------------------------------------------
// Kernel 1: CPB MLP -> bias table -> expand via rel_index (trivial cost)
// ---------------------------------------------------------------------------
__global__ void cpb_kernel(const float* __restrict__ cpb_w1,
                           const float* __restrict__ cpb_b1,
                           const float* __restrict__ cpb_w2,
                           const float* __restrict__ h_times,
                           const float* __restrict__ pow_para,
                           const float* __restrict__ ws1,
                           const float* __restrict__ ws2,
                           const int*   __restrict__ rel_index,
                           const float* __restrict__ coords)
{
    __shared__ float table[225 * 4];
    int t = threadIdx.x;
    if (t < 225) {
        float ht = log1pf(expf(h_times[0]));
        float pp = 1.0f / (1.0f + expf(-pow_para[0]));
        float ws = log1pf(expf(ws1[0])) / log1pf(expf(ws2[0]));
        float t0 = coords[t * 2 + 0] * ht;
        float t1 = coords[t * 2 + 1] * ht;
        float s0 = (float)((t0 > 0.f) - (t0 < 0.f));
        float s1 = (float)((t1 > 0.f) - (t1 < 0.f));
        t0 = s0 * powf(fabsf(t0) + 1e-6f, pp) * ws;
        t1 = s1 * powf(fabsf(t1) + 1e-6f, pp) * ws;
        float a0 = 0.f, a1 = 0.f, a2 = 0.f, a3 = 0.f;
        for (int j = 0; j < 512; j++) {
            float hsum = fmaf(t0, cpb_w1[j], fmaf(t1, cpb_w1[512 + j], cpb_b1[j]));
            hsum = fmaxf(hsum, 0.f);
            a0 = fmaf(hsum, cpb_w2[j * 4 + 0], a0);
            a1 = fmaf(hsum, cpb_w2[j * 4 + 1], a1);
            a2 = fmaf(hsum, cpb_w2[j * 4 + 2], a2);
            a3 = fmaf(hsum, cpb_w2[j * 4 + 3], a3);
        }
        table[t * 4 + 0] = a0; table[t * 4 + 1] = a1;
        table[t * 4 + 2] = a2; table[t * 4 + 3] = a3;
    }
    __syncthreads();
    for (int i = t; i < NHEADS * NTOK * NTOK; i += blockDim.x) {
        int h  = i / (NTOK * NTOK);
        int ij = i % (NTOK * NTOK);
        g_bias[i] = table[rel_index[ij] * 4 + h];
    }
}

// ---------------------------------------------------------------------------
// Kernel 2: fused window attention via mma.sync tf32 (A-split for accuracy)
// 1 window / CTA, 512 threads = 16 warps
// ---------------------------------------------------------------------------
__global__ void __launch_bounds__(512, 1)
attn_kernel(const float* __restrict__ x,
            const float* __restrict__ Wqkv,
            const float* __restrict__ Wproj,
            const float* __restrict__ bproj,
            float*       __restrict__ out)
{
    extern __shared__ float sm[];
    float* xs   = sm;                 // [64][132]  x, later O
    float* qs   = sm + 8448;          // [64][132]  q (tf32-rounded, pre-scaled)
    float* kT   = sm + 16896;         // [128][68]  k transposed [channel][token]
    float* vs   = sm + 25600;         // [64][132]  v (tf32-rounded)
    float* Sreg = sm + 34048;         // 4 x [64][68] scores per head
    float* Wbuf = Sreg;               // staging buffer (aliased; disjoint lifetime)

    const int tid  = threadIdx.x;
    const int lane = tid & 31;
    const int wid  = tid >> 5;
    const int lr   = lane >> 2;       // 0..7
    const int lc   = lane & 3;        // 0..3
    const int b    = blockIdx.x;

    // ---- load x tile ----
    const float4* xb = (const float4*)(x + (size_t)b * NTOK * DIM);
    #pragma unroll
    for (int i = 0; i < 4; i++) {
        int f = tid + i * 512;                 // 2048 float4s
        float4 v = xb[f];
        int r = f >> 5, c = (f & 31) << 2;
        float* p = xs + r * XS + c;
        p[0] = v.x; p[1] = v.y; p[2] = v.z; p[3] = v.w;
    }

    // =================== Phase 1: qkv = x @ Wqkv ===================
    // warp wid owns 24 output cols [24*wid, 24*wid+24): 4 m-tiles x 3 n-tiles
    {
        float acc[4][3][4];
        #pragma unroll
        for (int i = 0; i < 4; i++)
            #pragma unroll
            for (int j = 0; j < 3; j++)
                #pragma unroll
                for (int e = 0; e < 4; e++) acc[i][j][e] = 0.f;

        for (int kc = 0; kc < 8; kc++) {
            __syncthreads();
            // stage W rows [16*kc, 16*kc+16) x 384 into Wbuf
            #pragma unroll
            for (int i = 0; i < 3; i++) {
                int f = tid + i * 512;         // 1536 float4s
                int r = f / 96, c4 = f % 96;
                *(float4*)(Wbuf + r * WBS + c4 * 4) =
                    *(const float4*)(Wqkv + (size_t)(kc * 16 + r) * 384 + c4 * 4);
            }
            __syncthreads();

            #pragma unroll
            for (int ks = 0; ks < 2; ks++) {
                int kk = ks * 8;
                unsigned bf[3][2];
                #pragma unroll
                for (int j = 0; j < 3; j++) {
                    int n = wid * 24 + j * 8 + lr;
                    bf[j][0] = f2tf(Wbuf[(kk + lc) * WBS + n]);
                    bf[j][1] = f2tf(Wbuf[(kk + 4 + lc) * WBS + n]);
                }
                #pragma unroll
                for (int i = 0; i < 4; i++) {
                    int kbase = kc * 16 + kk;
                    float a0 = xs[(i * 16 + lr) * XS + kbase + lc];
                    float a1 = xs[(i * 16 + 8 + lr) * XS + kbase + lc];
                    float a2 = xs[(i * 16 + lr) * XS + kbase + 4 + lc];
                    float a3 = xs[(i * 16 + 8 + lr) * XS + kbase + 4 + lc];
                    unsigned ah[4] = { f2tf(a0), f2tf(a1), f2tf(a2), f2tf(a3) };
                    unsigned al[4] = { f2tf(a0 - uaf(ah[0])), f2tf(a1 - uaf(ah[1])),
                                       f2tf(a2 - uaf(ah[2])), f2tf(a3 - uaf(ah[3])) };
                    #pragma unroll
                    for (int j = 0; j < 3; j++) {
                        mma8(acc[i][j], ah, bf[j]);
                        mma8(acc[i][j], al, bf[j]);
                    }
                }
            }
        }
        __syncthreads();

        // scatter results to qs / kT / vs (tf32-rounded at store)
        #pragma unroll
        for (int j = 0; j < 3; j++) {
            int colbase = (wid * 3 + j) * 8;
            int panel = colbase >> 7;        // 0=q 1=k 2=v
            int pc = colbase & 127;
            #pragma unroll
            for (int i = 0; i < 4; i++) {
                #pragma unroll
                for (int eh = 0; eh < 2; eh++) {
                    int row = i * 16 + lr + 8 * eh;
                    float d0 = acc[i][j][2 * eh], d1 = acc[i][j][2 * eh + 1];
                    int cc = pc + 2 * lc;
                    if (panel == 0) {
                        qs[row * XS + cc]     = uaf(f2tf(d0 * SCALE));
                        qs[row * XS + cc + 1] = uaf(f2tf(d1 * SCALE));
                    } else if (panel == 1) {
                        kT[cc * KTS + row]       = uaf(f2tf(d0));
                        kT[(cc + 1) * KTS + row] = uaf(f2tf(d1));
                    } else {
                        vs[row * XS + cc]     = uaf(f2tf(d0));
                        vs[row * XS + cc + 1] = uaf(f2tf(d1));
                    }
                }
            }
        }
    }
    __syncthreads();

    // =================== Phase 2: S = Q K^T + bias ===================
    // 4 warps per head; warp owns 16 token-cols (2 n-tiles) x full M
    {
        const int h = wid >> 2, om = wid & 3;
        float acc[4][2][4];
        #pragma unroll
        for (int i = 0; i < 4; i++)
            #pragma unroll
            for (int j = 0; j < 2; j++)
                #pragma unroll
                for (int e = 0; e < 4; e++) acc[i][j][e] = 0.f;

        #pragma unroll
        for (int ks = 0; ks < 4; ks++) {
            int kk = h * 32 + ks * 8;
            unsigned bf[2][2];
            #pragma unroll
            for (int j = 0; j < 2; j++) {
                int n = om * 16 + j * 8 + lr;
                bf[j][0] = fau(kT[(kk + lc) * KTS + n]);
                bf[j][1] = fau(kT[(kk + 4 + lc) * KTS + n]);
            }
            #pragma unroll
            for (int i = 0; i < 4; i++) {
                unsigned af[4] = {
                    fau(qs[(i * 16 + lr) * XS + kk + lc]),
                    fau(qs[(i * 16 + 8 + lr) * XS + kk + lc]),
                    fau(qs[(i * 16 + lr) * XS + kk + 4 + lc]),
                    fau(qs[(i * 16 + 8 + lr) * XS + kk + 4 + lc]) };
                #pragma unroll
                for (int j = 0; j < 2; j++) mma8(acc[i][j], af, bf[j]);
            }
        }

        float* Sh = Sreg + h * (NTOK * SS);
        const float* bh = g_bias + h * NTOK * NTOK;
        #pragma unroll
        for (int i = 0; i < 4; i++)
            #pragma unroll
            for (int j = 0; j < 2; j++) {
                int n0 = om * 16 + j * 8 + 2 * lc;
                #pragma unroll
                for (int eh = 0; eh < 2; eh++) {
                    int row = i * 16 + lr + 8 * eh;
                    float2 bv = *(const float2*)(bh + row * 64 + n0);
                    float2 sv = make_float2(acc[i][j][2 * eh] + bv.x,
                                            acc[i][j][2 * eh + 1] + bv.y);
                    *(float2*)(Sh + row * SS + n0) = sv;
                }
            }
    }
    __syncthreads();

    // =================== Phase 3: softmax (rows of S) ===================
    {
        int h = tid >> 7;
        int row = (tid >> 1) & 63;
        int half = tid & 1;
        float* sr = Sreg + h * (NTOK * SS) + row * SS + half * 32;
        float v[32];
        float mx = -1e30f;
        #pragma unroll
        for (int j = 0; j < 32; j++) { v[j] = sr[j]; mx = fmaxf(mx, v[j]); }
        mx = fmaxf(mx, __shfl_xor_sync(0xffffffffu, mx, 1));
        float sum = 0.f;
        #pragma unroll
        for (int j = 0; j < 32; j++) { v[j] = __expf(v[j] - mx); sum += v[j]; }
        sum += __shfl_xor_sync(0xffffffffu, sum, 1);
        float inv = 1.0f / sum;
        #pragma unroll
        for (int j = 0; j < 32; j++) sr[j] = v[j] * inv;
    }
    __syncthreads();

    // =================== Phase 4: O = P V (into xs) ===================
    // 4 warps per head; warp owns 8 channel-cols (1 n-tile)
    {
        const int h = wid >> 2, om = wid & 3;
        const float* Sh = Sreg + h * (NTOK * SS);
        float acc[4][4];
        #pragma unroll
        for (int i = 0; i < 4; i++)
            #pragma unroll
            for (int e = 0; e < 4; e++) acc[i][e] = 0.f;

        #pragma unroll
        for (int ks = 0; ks < 8; ks++) {
            int kk = ks * 8;
            int n = h * 32 + om * 8 + lr;
            unsigned bf[2];
            bf[0] = fau(vs[(kk + lc) * XS + n]);
            bf[1] = fau(vs[(kk + 4 + lc) * XS + n]);
            #pragma unroll
            for (int i = 0; i < 4; i++) {
                float p0 = Sh[(i * 16 + lr) * SS + kk + lc];
                float p1 = Sh[(i * 16 + 8 + lr) * SS + kk + lc];
                float p2 = Sh[(i * 16 + lr) * SS + kk + 4 + lc];
                float p3 = Sh[(i * 16 + 8 + lr) * SS + kk + 4 + lc];
                unsigned ph[4] = { f2tf(p0), f2tf(p1), f2tf(p2), f2tf(p3) };
                unsigned pl[4] = { f2tf(p0 - uaf(ph[0])), f2tf(p1 - uaf(ph[1])),
                                   f2tf(p2 - uaf(ph[2])), f2tf(p3 - uaf(ph[3])) };
                mma8(acc[i], ph, bf);
                mma8(acc[i], pl, bf);
            }
        }

        int base = h * 32 + om * 8 + 2 * lc;
        #pragma unroll
        for (int i = 0; i < 4; i++) {
            #pragma unroll
            for (int eh = 0; eh < 2; eh++) {
                int row = i * 16 + lr + 8 * eh;
                *(float2*)(xs + row * XS + base) =
                    make_float2(acc[i][2 * eh], acc[i][2 * eh + 1]);
            }
        }
    }
    __syncthreads();

    // =================== Phase 5: Y = O @ Wproj + b ===================
    // warp wid owns 8 output cols (1 n-tile)
    {
        float acc[4][4];
        #pragma unroll
        for (int i = 0; i < 4; i++)
            #pragma unroll
            for (int e = 0; e < 4; e++) acc[i][e] = 0.f;

        for (int kc = 0; kc < 8; kc++) {
            __syncthreads();
            // stage Wproj rows [16*kc, +16) x 128 (stride 132)
            {
                int r = tid >> 5, c4 = tid & 31;
                *(float4*)(Wbuf + r * XS + c4 * 4) =
                    *(const float4*)(Wproj + (size_t)(kc * 16 + r) * 128 + c4 * 4);
            }
            __syncthreads();

            #pragma unroll
            for (int ks = 0; ks < 2; ks++) {
                int kk = ks * 8;
                int n = wid * 8 + lr;
                unsigned bf[2];
                bf[0] = f2tf(Wbuf[(kk + lc) * XS + n]);
                bf[1] = f2tf(Wbuf[(kk + 4 + lc) * XS + n]);
                #pragma unroll
                for (int i = 0; i < 4; i++) {
                    int kbase = kc * 16 + kk;
                    float a0 = xs[(i * 16 + lr) * XS + kbase + lc];
                    float a1 = xs[(i * 16 + 8 + lr) * XS + kbase + lc];
                    float a2 = xs[(i * 16 + lr) * XS + kbase + 4 + lc];
                    float a3 = xs[(i * 16 + 8 + lr) * XS + kbase + 4 + lc];
                    unsigned ah[4] = { f2tf(a0), f2tf(a1), f2tf(a2), f2tf(a3) };
                    unsigned al[4] = { f2tf(a0 - uaf(ah[0])), f2tf(a1 - uaf(ah[1])),
                                       f2tf(a2 - uaf(ah[2])), f2tf(a3 - uaf(ah[3])) };
                    mma8(acc[i], ah, bf);
                    mma8(acc[i], al, bf);
                }
            }
        }

        float* ob = out + (size_t)b * NTOK * DIM;
        float2 bb = *(const float2*)(bproj + wid * 8 + 2 * lc);
        #pragma unroll
        for (int i = 0; i < 4; i++) {
            #pragma unroll
            for (int eh = 0; eh < 2; eh++) {
                int row = i * 16 + lr + 8 * eh;
                *(float2*)(ob + row * 128 + wid * 8 + 2 * lc) =
                    make_float2(acc[i][2 * eh] + bb.x, acc[i][2 * eh + 1] + bb.y);
            }
        }
    }
}

// ---------------------------------------------------------------------------
// Launch
// ---------------------------------------------------------------------------
extern "C" void kernel_launch(void* const* d_in, const int* in_sizes, int n_in,
                              void* d_out, int out_size)
{
    const float* x        = (const float*)d_in[0];
    const float* Wqkv     = (const float*)d_in[1];
    const float* Wproj    = (const float*)d_in[2];
    const float* bproj    = (const float*)d_in[3];
    const float* cpb_w1   = (const float*)d_in[4];
    const float* cpb_b1   = (const float*)d_in[5];
    const float* cpb_w2   = (const float*)d_in[6];
    const float* h_times  = (const float*)d_in[7];
    const float* pow_para = (const float*)d_in[8];
    const float* ws1      = (const float*)d_in[9];
    const float* ws2      = (const float*)d_in[10];
    const int*   rel_idx  = (const int*)d_in[11];
    const float* coords   = (const float*)d_in[12];

    int nwin = in_sizes[0] / (NTOK * DIM);

    // 8448*4 + 8704 + 8448 + 17408 floats = 51456 floats
    int smem_bytes = 51456 * (int)sizeof(float);
    cudaFuncSetAttribute(attn_kernel,
                         cudaFuncAttributeMaxDynamicSharedMemorySize, smem_bytes);

    cpb_kernel<<<1, 256>>>(cpb_w1, cpb_b1, cpb_w2, h_times, pow_para,
                           ws1, ws2, rel_idx, coords);
    attn_kernel<<<nwin, 512, smem_bytes>>>(x, Wqkv, Wproj, bproj, (float*)d_out);
}

// round 4
// speedup vs baseline: 1.6730x; 1.0198x over previous
#include <cuda_runtime.h>
#include <math.h>

#define NTOK 64
#define DIM 128
#define NHEADS 4
#define SCALE 0.1767766952966369f   // 32^-0.5

// smem strides / offsets (floats)
#define XPS 260          // xp row stride: 16 kgroups * 16 + 4 pad
#define QSS 130          // qs row stride
#define KTS2 136         // kTp (g,lc)-row stride (68 float2)
#define VSS2 264         // vsp (tg,tl)-row stride (132 float2)
#define SSS 66           // Ss row stride
#define WQS 776          // Wqkv packed row stride (388 float2)
#define WPS 264          // Wproj packed row stride (132 float2)

#define OFF_XP   0                   // 64*260      = 16640  (x hi/lo packed; later O hi/lo)
#define OFF_QS   16640               // 64*130      = 8320
#define OFF_KT   24960               // 64*136      = 8704
#define OFF_SS   16640               // 4*64*66     = 16896  (aliases qs+kTp)
#define OFF_VS   33664               // 32*264      = 8448
#define OFF_WST  42112               // 6208 staging
#define SMEM_FLOATS 48320

__device__ float g_bias[NHEADS * NTOK * NTOK];
__device__ float g_wqkv_p[64 * WQS];    // packed tf32 Wqkv: [(g*4+lc)][n] -> (W[8g+lc][n], W[8g+4+lc][n])
__device__ float g_wproj_p[64 * WPS];   // packed tf32 Wproj

__device__ __forceinline__ unsigned f2tf(float x) {
    unsigned r; asm("cvt.rna.tf32.f32 %0, %1;" : "=r"(r) : "f"(x)); return r;
}
__device__ __forceinline__ float uaf(unsigned x) { return __uint_as_float(x); }
__device__ __forceinline__ unsigned fau(float x) { return __float_as_uint(x); }

__device__ __forceinline__ void mma8(float* c, const unsigned* a, const unsigned* b) {
    asm volatile(
        "mma.sync.aligned.m16n8k8.row.col.f32.tf32.tf32.f32 "
        "{%0,%1,%2,%3}, {%4,%5,%6,%7}, {%8,%9}, {%0,%1,%2,%3};"
        : "+f"(c[0]), "+f"(c[1]), "+f"(c[2]), "+f"(c[3])
        : "r"(a[0]), "r"(a[1]), "r"(a[2]), "r"(a[3]), "r"(b[0]), "r"(b[1]));
}

// ---------------------------------------------------------------------------
// Setup kernel A: CPB MLP -> bias table -> expand via rel_index
// ---------------------------------------------------------------------------
__global__ void cpb_kernel(const float* __restrict__ cpb_w1,
                           const float* __restrict__ cpb_b1,
                           const float* __restrict__ cpb_w2,
                           const float* __restrict__ h_times,
                           const float* __restrict__ pow_para,
                           const float* __restrict__ ws1,
                           const float* __restrict__ ws2,
                           const int*   __restrict__ rel_index,
                           const float* __restrict__ coords)
{
    __shared__ float table[225 * 4];
    int t = threadIdx.x;
    if (t < 225) {
        float ht = log1pf(expf(h_times[0]));
        float pp = 1.0f / (1.0f + expf(-pow_para[0]));
        float ws = log1pf(expf(ws1[0])) / log1pf(expf(ws2[0]));
        float t0 = coords[t * 2 + 0] * ht;
        float t1 = coords[t * 2 + 1] * ht;
        float s0 = (float)((t0 > 0.f) - (t0 < 0.f));
        float s1 = (float)((t1 > 0.f) - (t1 < 0.f));
        t0 = s0 * powf(fabsf(t0) + 1e-6f, pp) * ws;
        t1 = s1 * powf(fabsf(t1) + 1e-6f, pp) * ws;
        float a0 = 0.f, a1 = 0.f, a2 = 0.f, a3 = 0.f;
        for (int j = 0; j < 512; j++) {
            float hsum = fmaf(t0, cpb_w1[j], fmaf(t1, cpb_w1[512 + j], cpb_b1[j]));
            hsum = fmaxf(hsum, 0.f);
            a0 = fmaf(hsum, cpb_w2[j * 4 + 0], a0);
            a1 = fmaf(hsum, cpb_w2[j * 4 + 1], a1);
            a2 = fmaf(hsum, cpb_w2[j * 4 + 2], a2);
            a3 = fmaf(hsum, cpb_w2[j * 4 + 3], a3);
        }
        table[t * 4 + 0] = a0; table[t * 4 + 1] = a1;
        table[t * 4 + 2] = a2; table[t * 4 + 3] = a3;
    }
    __syncthreads();
    for (int i = t; i < NHEADS * NTOK * NTOK; i += blockDim.x) {
        int h  = i / (NTOK * NTOK);
        int ij = i % (NTOK * NTOK);
        g_bias[i] = table[rel_index[ij] * 4 + h];
    }
}

// ---------------------------------------------------------------------------
// Setup kernel B: round weights to tf32 and pack into B-fragment order
// ---------------------------------------------------------------------------
__global__ void pack_kernel(const float* __restrict__ Wqkv,
                            const float* __restrict__ Wproj)
{
    int tid = blockIdx.x * blockDim.x + threadIdx.x;
    int stride = gridDim.x * blockDim.x;
    for (int i = tid; i < 64 * 384; i += stride) {
        int r = i / 384, n = i % 384;
        int g = r >> 2, lc = r & 3;
        float2 v;
        v.x = uaf(f2tf(Wqkv[(size_t)(8 * g + lc) * 384 + n]));
        v.y = uaf(f2tf(Wqkv[(size_t)(8 * g + lc + 4) * 384 + n]));
        *(float2*)(g_wqkv_p + r * WQS + n * 2) = v;
    }
    for (int i = tid; i < 64 * 128; i += stride) {
        int r = i / 128, n = i % 128;
        int g = r >> 2, lc = r & 3;
        float2 v;
        v.x = uaf(f2tf(Wproj[(size_t)(8 * g + lc) * 128 + n]));
        v.y = uaf(f2tf(Wproj[(size_t)(8 * g + lc + 4) * 128 + n]));
        *(float2*)(g_wproj_p + r * WPS + n * 2) = v;
    }
}

// ---------------------------------------------------------------------------
// Main fused kernel: 1 window / CTA, 512 threads = 16 warps
// ---------------------------------------------------------------------------
__global__ void __launch_bounds__(512, 1)
attn_kernel(const float* __restrict__ x,
            const float* __restrict__ bproj,
            float*       __restrict__ out)
{
    extern __shared__ float sm[];
    float* xp  = sm + OFF_XP;
    float* qs  = sm + OFF_QS;
    float* kTp = sm + OFF_KT;
    float* Ss  = sm + OFF_SS;
    float* vsp = sm + OFF_VS;
    float* Wst = sm + OFF_WST;

    const int tid  = threadIdx.x;
    const int lane = tid & 31;
    const int wid  = tid >> 5;
    const int lr   = lane >> 2;       // 0..7
    const int lc   = lane & 3;        // 0..3
    const int b    = blockIdx.x;
    const int mi   = wid & 3;         // m-tile for phases 1/5
    const int nq   = wid >> 2;        // n-quarter for phases 1/5

    // ---- load x, split into (hi, lo) tf32 pairs, packed layout ----
    // xp[row][g][lc] = float4(hi(k=8g+lc), lo, hi(k=8g+4+lc), lo)
    const float4* xb = (const float4*)(x + (size_t)b * NTOK * DIM);
    #pragma unroll
    for (int i = 0; i < 4; i++) {
        int f = tid + i * 512;
        float4 v = xb[f];
        int r = f >> 5, c0 = (f & 31) << 2;
        float* p = xp + r * XPS + (c0 >> 3) * 16 + ((c0 >> 2) & 1) * 2;
        float vv[4] = { v.x, v.y, v.z, v.w };
        #pragma unroll
        for (int e = 0; e < 4; e++) {
            float hi = uaf(f2tf(vv[e]));
            float lo = uaf(f2tf(vv[e] - hi));
            p[e * 4]     = hi;
            p[e * 4 + 1] = lo;
        }
    }

    // =================== Phase 1: qkv = x @ Wqkv ===================
    // warp (mi, nq): m-tile mi, 96 cols [nq*96, +96) = 12 n-tiles
    {
        float acc[12][4];
        #pragma unroll
        for (int j = 0; j < 12; j++)
            #pragma unroll
            for (int e = 0; e < 4; e++) acc[j][e] = 0.f;

        for (int kc = 0; kc < 8; kc++) {
            __syncthreads();
            const float4* src = (const float4*)(g_wqkv_p + kc * (2 * 4 * WQS));
            #pragma unroll
            for (int i = tid; i < 1552; i += 512)
                ((float4*)Wst)[i] = src[i];
            __syncthreads();

            #pragma unroll
            for (int gs = 0; gs < 2; gs++) {
                const float* pa = xp + (mi * 16 + lr) * XPS + (kc * 2 + gs) * 16 + lc * 4;
                float4 a0 = *(const float4*)pa;
                float4 a1 = *(const float4*)(pa + 8 * XPS);
                unsigned ah[4] = { fau(a0.x), fau(a1.x), fau(a0.z), fau(a1.z) };
                unsigned al[4] = { fau(a0.y), fau(a1.y), fau(a0.w), fau(a1.w) };
                const float* wrow = Wst + (gs * 4 + lc) * WQS;
                #pragma unroll
                for (int j = 0; j < 12; j++) {
                    int n = nq * 96 + j * 8 + lr;
                    float2 bw = *(const float2*)(wrow + n * 2);
                    unsigned bf[2] = { fau(bw.x), fau(bw.y) };
                    mma8(acc[j], ah, bf);
                    mma8(acc[j], al, bf);
                }
            }
        }

        // scatter to qs / kTp / vsp (tf32-rounded)
        #pragma unroll
        for (int j = 0; j < 12; j++) {
            int colbase = nq * 96 + j * 8;
            int panel = colbase >> 7;
            int pc = colbase & 127;
            #pragma unroll
            for (int eh = 0; eh < 2; eh++) {
                int row = mi * 16 + lr + 8 * eh;
                #pragma unroll
                for (int e = 0; e < 2; e++) {
                    float val = acc[j][2 * eh + e];
                    int cc = pc + 2 * lc + e;
                    if (panel == 0) {
                        qs[row * QSS + cc] = uaf(f2tf(val * SCALE));
                    } else if (panel == 1) {
                        kTp[((cc >> 3) * 4 + (cc & 3)) * KTS2 + row * 2 + ((cc >> 2) & 1)]
                            = uaf(f2tf(val));
                    } else {
                        vsp[((row >> 3) * 4 + (row & 3)) * VSS2 + cc * 2 + ((row >> 2) & 1)]
                            = uaf(f2tf(val));
                    }
                }
            }
        }
    }
    __syncthreads();

    // =================== Phase 2: S = Q K^T + bias ===================
    // 4 warps per head (h = wid>>2, om = wid&3): warp owns 16 token-cols
    {
        const int h = wid >> 2, om = wid & 3;
        float acc[4][2][4];
        #pragma unroll
        for (int i = 0; i < 4; i++)
            #pragma unroll
            for (int j = 0; j < 2; j++)
                #pragma unroll
                for (int e = 0; e < 4; e++) acc[i][j][e] = 0.f;

        #pragma unroll
        for (int ks = 0; ks < 4; ks++) {
            int kk = h * 32 + ks * 8;
            const float* krow = kTp + ((kk >> 3) * 4 + lc) * KTS2;
            unsigned bf[2][2];
            #pragma unroll
            for (int j = 0; j < 2; j++) {
                int n = om * 16 + j * 8 + lr;
                float2 kv = *(const float2*)(krow + n * 2);
                bf[j][0] = fau(kv.x); bf[j][1] = fau(kv.y);
            }
            #pragma unroll
            for (int i = 0; i < 4; i++) {
                unsigned af[4] = {
                    fau(qs[(i * 16 + lr) * QSS + kk + lc]),
                    fau(qs[(i * 16 + 8 + lr) * QSS + kk + lc]),
                    fau(qs[(i * 16 + lr) * QSS + kk + 4 + lc]),
                    fau(qs[(i * 16 + 8 + lr) * QSS + kk + 4 + lc]) };
                #pragma unroll
                for (int j = 0; j < 2; j++) mma8(acc[i][j], af, bf[j]);
            }
        }

        __syncthreads();   // all qs/kTp reads done: Ss aliases that memory

        float* Sh = Ss + h * (NTOK * SSS);
        const float* bh = g_bias + h * NTOK * NTOK;
        #pragma unroll
        for (int i = 0; i < 4; i++)
            #pragma unroll
            for (int j = 0; j < 2; j++) {
                int n0 = om * 16 + j * 8 + 2 * lc;
                #pragma unroll
                for (int eh = 0; eh < 2; eh++) {
                    int row = i * 16 + lr + 8 * eh;
                    float2 bv = *(const float2*)(bh + row * 64 + n0);
                    *(float2*)(Sh + row * SSS + n0) =
                        make_float2(acc[i][j][2 * eh] + bv.x,
                                    acc[i][j][2 * eh + 1] + bv.y);
                }
            }
    }
    __syncthreads();

    // =================== Phase 3: softmax (rounds P to tf32) ===================
    {
        int h = tid >> 7;
        int row = (tid >> 1) & 63;
        int half = tid & 1;
        float* sr = Ss + h * (NTOK * SSS) + row * SSS + half * 32;
        float v[32];
        float mx = -1e30f;
        #pragma unroll
        for (int j = 0; j < 32; j++) { v[j] = sr[j]; mx = fmaxf(mx, v[j]); }
        mx = fmaxf(mx, __shfl_xor_sync(0xffffffffu, mx, 1));
        float sum = 0.f;
        #pragma unroll
        for (int j = 0; j < 32; j++) { v[j] = __expf(v[j] - mx); sum += v[j]; }
        sum += __shfl_xor_sync(0xffffffffu, sum, 1);
        float inv = 1.0f / sum;
        #pragma unroll
        for (int j = 0; j < 32; j++) sr[j] = uaf(f2tf(v[j] * inv));
    }
    __syncthreads();

    // =================== Phase 4: O = P V, split+pack into xp ===================
    {
        const int h = wid >> 2, om = wid & 3;
        const float* Sh = Ss + h * (NTOK * SSS);
        float acc[4][4];
        #pragma unroll
        for (int i = 0; i < 4; i++)
            #pragma unroll
            for (int e = 0; e < 4; e++) acc[i][e] = 0.f;

        #pragma unroll
        for (int ks = 0; ks < 8; ks++) {
            int kk = ks * 8;
            int n = h * 32 + om * 8 + lr;
            float2 vv = *(const float2*)(vsp + (ks * 4 + lc) * VSS2 + n * 2);
            unsigned bf[2] = { fau(vv.x), fau(vv.y) };
            #pragma unroll
            for (int i = 0; i < 4; i++) {
                unsigned pf[4] = {
                    fau(Sh[(i * 16 + lr) * SSS + kk + lc]),
                    fau(Sh[(i * 16 + 8 + lr) * SSS + kk + lc]),
                    fau(Sh[(i * 16 + lr) * SSS + kk + 4 + lc]),
                    fau(Sh[(i * 16 + 8 + lr) * SSS + kk + 4 + lc]) };
                mma8(acc[i], pf, bf);
            }
        }

        #pragma unroll
        for (int i = 0; i < 4; i++)
            #pragma unroll
            for (int eh = 0; eh < 2; eh++) {
                int row = i * 16 + lr + 8 * eh;
                #pragma unroll
                for (int e = 0; e < 2; e++) {
                    int ch = h * 32 + om * 8 + 2 * lc + e;
                    float o = acc[i][2 * eh + e];
                    float hi = uaf(f2tf(o));
                    float lo = uaf(f2tf(o - hi));
                    float* p = xp + row * XPS + (ch >> 3) * 16 + (ch & 3) * 4
                             + ((ch >> 2) & 1) * 2;
                    p[0] = hi; p[1] = lo;
                }
            }
    }
    __syncthreads();

    // =================== Phase 5: Y = O @ Wproj + b ===================
    // warp (mi, nq): m-tile mi, 32 cols [nq*32, +32) = 4 n-tiles
    {
        float acc[4][4];
        #pragma unroll
        for (int j = 0; j < 4; j++)
            #pragma unroll
            for (int e = 0; e < 4; e++) acc[j][e] = 0.f;

        for (int kc = 0; kc < 8; kc++) {
            __syncthreads();
            const float4* src = (const float4*)(g_wproj_p + kc * (2 * 4 * WPS));
            #pragma unroll
            for (int i = tid; i < 528; i += 512)
                ((float4*)Wst)[i] = src[i];
            __syncthreads();

            #pragma unroll
            for (int gs = 0; gs < 2; gs++) {
                const float* pa = xp + (mi * 16 + lr) * XPS + (kc * 2 + gs) * 16 + lc * 4;
                float4 a0 = *(const float4*)pa;
                float4 a1 = *(const float4*)(pa + 8 * XPS);
                unsigned ah[4] = { fau(a0.x), fau(a1.x), fau(a0.z), fau(a1.z) };
                unsigned al[4] = { fau(a0.y), fau(a1.y), fau(a0.w), fau(a1.w) };
                const float* wrow = Wst + (gs * 4 + lc) * WPS;
                #pragma unroll
                for (int j = 0; j < 4; j++) {
                    int n = nq * 32 + j * 8 + lr;
                    float2 bw = *(const float2*)(wrow + n * 2);
                    unsigned bf[2] = { fau(bw.x), fau(bw.y) };
                    mma8(acc[j], ah, bf);
                    mma8(acc[j], al, bf);
                }
            }
        }

        float* ob = out + (size_t)b * NTOK * DIM;
        #pragma unroll
        for (int j = 0; j < 4; j++) {
            int c0 = nq * 32 + j * 8 + 2 * lc;
            float2 bb = *(const float2*)(bproj + c0);
            #pragma unroll
            for (int eh = 0; eh < 2; eh++) {
                int row = mi * 16 + lr + 8 * eh;
                *(float2*)(ob + row * DIM + c0) =
                    make_float2(acc[j][2 * eh] + bb.x, acc[j][2 * eh + 1] + bb.y);
            }
        }
    }
}

// ---------------------------------------------------------------------------
// Launch
// ---------------------------------------------------------------------------
extern "C" void kernel_launch(void* const* d_in, const int* in_sizes, int n_in,
                              void* d_out, int out_size)
{
    const float* x        = (const float*)d_in[0];
    const float* Wqkv     = (const float*)d_in[1];
    const float* Wproj    = (const float*)d_in[2];
    const float* bproj    = (const float*)d_in[3];
    const float* cpb_w1   = (const float*)d_in[4];
    const float* cpb_b1   = (const float*)d_in[5];
    const float* cpb_w2   = (const float*)d_in[6];
    const float* h_times  = (const float*)d_in[7];
    const float* pow_para = (const float*)d_in[8];
    const float* ws1      = (const float*)d_in[9];
    const float* ws2      = (const float*)d_in[10];
    const int*   rel_idx  = (const int*)d_in[11];
    const float* coords   = (const float*)d_in[12];

    int nwin = in_sizes[0] / (NTOK * DIM);

    int smem_bytes = SMEM_FLOATS * (int)sizeof(float);
    cudaFuncSetAttribute(attn_kernel,
                         cudaFuncAttributeMaxDynamicSharedMemorySize, smem_bytes);

    cpb_kernel<<<1, 256>>>(cpb_w1, cpb_b1, cpb_w2, h_times, pow_para,
                           ws1, ws2, rel_idx, coords);
    pack_kernel<<<96, 256>>>(Wqkv, Wproj);
    attn_kernel<<<nwin, 512, smem_bytes>>>(x, bproj, (float*)d_out);
}

// round 5
// speedup vs baseline: 2.5261x; 1.5099x over previous
#include <cuda_runtime.h>
#include <math.h>

#define NTOK 64
#define DIM 128
#define NHEADS 4
#define SCALE 0.1767766952966369f   // 32^-0.5

// smem strides (floats)
#define XPS 132          // xp row stride (packed (k,k+4) pairs, 16 groups * 8 + 4 pad)
#define QSS 132          // qs row stride (same packing)
#define KTS2 136         // kTp row stride: 64 rows (g*4+lc) x 136 (68 float2)
#define VSS2 264         // vsp row stride: 32 rows (tg*4+tl) x 264 (132 float2)
#define SSS 66           // Ss row stride
#define WQS 776          // packed Wqkv row stride (384 float2 + pad)
#define WPS 264          // packed Wproj row stride (128 float2 + pad)

#define OFF_XP 0                     // 64*132 = 8448   x (tf32), later O (tf32)
#define OFF_QS 8448                  // 64*132 = 8448
#define OFF_KT 16896                 // 64*136 = 8704
#define OFF_SS 8448                  // 4*64*66 = 16896 (aliases qs+kTp, <= 17152)
#define OFF_VS 25600                 // 32*264 = 8448
#define SMEM_FLOATS 34048            // 136 KB

__device__ float g_table[225 * 4];
__device__ float g_bias[NHEADS * NTOK * NTOK];
__device__ float g_wqkv_p[64 * WQS];   // [(g*4+lc)][n] -> (tf32 W[8g+lc][n], tf32 W[8g+4+lc][n])
__device__ float g_wproj_p[64 * WPS];

__device__ __forceinline__ unsigned f2tf(float x) {
    unsigned r; asm("cvt.rna.tf32.f32 %0, %1;" : "=r"(r) : "f"(x)); return r;
}
__device__ __forceinline__ float uaf(unsigned x) { return __uint_as_float(x); }
__device__ __forceinline__ unsigned fau(float x) { return __float_as_uint(x); }

__device__ __forceinline__ void mma8(float* c, const unsigned* a, const unsigned* b) {
    asm volatile(
        "mma.sync.aligned.m16n8k8.row.col.f32.tf32.tf32.f32 "
        "{%0,%1,%2,%3}, {%4,%5,%6,%7}, {%8,%9}, {%0,%1,%2,%3};"
        : "+f"(c[0]), "+f"(c[1]), "+f"(c[2]), "+f"(c[3])
        : "r"(a[0]), "r"(a[1]), "r"(a[2]), "r"(a[3]), "r"(b[0]), "r"(b[1]));
}

// ---------------------------------------------------------------------------
// Setup A1: CPB table — one block per coordinate point, parallel over hidden
// ---------------------------------------------------------------------------
__global__ void cpb_table_kernel(const float* __restrict__ cpb_w1,
                                 const float* __restrict__ cpb_b1,
                                 const float* __restrict__ cpb_w2,
                                 const float* __restrict__ h_times,
                                 const float* __restrict__ pow_para,
                                 const float* __restrict__ ws1,
                                 const float* __restrict__ ws2,
                                 const float* __restrict__ coords)
{
    __shared__ float red[128][4];
    const int t = blockIdx.x;          // 0..224
    const int tid = threadIdx.x;       // 0..127

    float ht = log1pf(expf(h_times[0]));
    float pp = 1.0f / (1.0f + expf(-pow_para[0]));
    float ws = log1pf(expf(ws1[0])) / log1pf(expf(ws2[0]));
    float t0 = coords[t * 2 + 0] * ht;
    float t1 = coords[t * 2 + 1] * ht;
    float s0 = (float)((t0 > 0.f) - (t0 < 0.f));
    float s1 = (float)((t1 > 0.f) - (t1 < 0.f));
    t0 = s0 * powf(fabsf(t0) + 1e-6f, pp) * ws;
    t1 = s1 * powf(fabsf(t1) + 1e-6f, pp) * ws;

    float a0 = 0.f, a1 = 0.f, a2 = 0.f, a3 = 0.f;
    for (int j = tid; j < 512; j += 128) {
        float hsum = fmaf(t0, cpb_w1[j], fmaf(t1, cpb_w1[512 + j], cpb_b1[j]));
        hsum = fmaxf(hsum, 0.f);
        a0 = fmaf(hsum, cpb_w2[j * 4 + 0], a0);
        a1 = fmaf(hsum, cpb_w2[j * 4 + 1], a1);
        a2 = fmaf(hsum, cpb_w2[j * 4 + 2], a2);
        a3 = fmaf(hsum, cpb_w2[j * 4 + 3], a3);
    }
    red[tid][0] = a0; red[tid][1] = a1; red[tid][2] = a2; red[tid][3] = a3;
    __syncthreads();
    for (int s = 64; s > 0; s >>= 1) {
        if (tid < s) {
            red[tid][0] += red[tid + s][0];
            red[tid][1] += red[tid + s][1];
            red[tid][2] += red[tid + s][2];
            red[tid][3] += red[tid + s][3];
        }
        __syncthreads();
    }
    if (tid < 4) g_table[t * 4 + tid] = red[0][tid];
}

// ---------------------------------------------------------------------------
// Setup A2: expand bias via rel_index
// ---------------------------------------------------------------------------
__global__ void bias_expand_kernel(const int* __restrict__ rel_index)
{
    int ij = blockIdx.x * blockDim.x + threadIdx.x;
    if (ij < NTOK * NTOK) {
        int ri = rel_index[ij];
        #pragma unroll
        for (int h = 0; h < 4; h++)
            g_bias[h * NTOK * NTOK + ij] = g_table[ri * 4 + h];
    }
}

// ---------------------------------------------------------------------------
// Setup B: round weights to tf32, pack into B-fragment order
// ---------------------------------------------------------------------------
__global__ void pack_kernel(const float* __restrict__ Wqkv,
                            const float* __restrict__ Wproj)
{
    int tid = blockIdx.x * blockDim.x + threadIdx.x;
    int stride = gridDim.x * blockDim.x;
    for (int i = tid; i < 64 * 384; i += stride) {
        int r = i / 384, n = i % 384;
        int g = r >> 2, lc = r & 3;
        float2 v;
        v.x = uaf(f2tf(Wqkv[(size_t)(8 * g + lc) * 384 + n]));
        v.y = uaf(f2tf(Wqkv[(size_t)(8 * g + lc + 4) * 384 + n]));
        *(float2*)(g_wqkv_p + r * WQS + n * 2) = v;
    }
    for (int i = tid; i < 64 * 128; i += stride) {
        int r = i / 128, n = i % 128;
        int g = r >> 2, lc = r & 3;
        float2 v;
        v.x = uaf(f2tf(Wproj[(size_t)(8 * g + lc) * 128 + n]));
        v.y = uaf(f2tf(Wproj[(size_t)(8 * g + lc + 4) * 128 + n]));
        *(float2*)(g_wproj_p + r * WPS + n * 2) = v;
    }
}

// ---------------------------------------------------------------------------
// Main fused kernel: 1 window / CTA, 512 threads = 16 warps
// ---------------------------------------------------------------------------
__global__ void __launch_bounds__(512, 1)
attn_kernel(const float* __restrict__ x,
            const float* __restrict__ bproj,
            float*       __restrict__ out)
{
    extern __shared__ float sm[];
    float* xp  = sm + OFF_XP;     // tf32 x, later tf32 O; packed (k,k+4) pairs
    float* qs  = sm + OFF_QS;     // tf32 q*scale, packed pairs
    float* kTp = sm + OFF_KT;     // tf32 k, B-fragment layout
    float* Ss  = sm + OFF_SS;     // scores (aliases qs+kTp)
    float* vsp = sm + OFF_VS;     // tf32 v, B-fragment layout

    const int tid  = threadIdx.x;
    const int lane = tid & 31;
    const int wid  = tid >> 5;
    const int lr   = lane >> 2;   // 0..7
    const int lc   = lane & 3;    // 0..3
    const int b    = blockIdx.x;
    const int mi   = wid & 3;     // m-tile (phases 1/5)
    const int nq   = wid >> 2;    // n-quarter (phases 1/5)

    // ---- load x, round to tf32, packed (k, k+4) pair layout ----
    // xp[row*XPS + g*8 + lc*2 + s], k = 8g + 4s + lc
    const float4* xb = (const float4*)(x + (size_t)b * NTOK * DIM);
    #pragma unroll
    for (int i = 0; i < 4; i++) {
        int f = tid + i * 512;
        float4 v = xb[f];
        int r = f >> 5, c0 = (f & 31) << 2;     // c0 multiple of 4
        int g = c0 >> 3, s = (c0 >> 2) & 1;
        float* p = xp + r * XPS + g * 8 + s;
        p[0] = uaf(f2tf(v.x));
        p[2] = uaf(f2tf(v.y));
        p[4] = uaf(f2tf(v.z));
        p[6] = uaf(f2tf(v.w));
    }
    __syncthreads();

    // =================== Phase 1: qkv = tf32(x) @ tf32(Wqkv) ===================
    // warp (mi, nq): m-tile mi, cols [nq*96, +96) = 12 n-tiles; B direct LDG
    {
        float acc[12][4];
        #pragma unroll
        for (int j = 0; j < 12; j++)
            #pragma unroll
            for (int e = 0; e < 4; e++) acc[j][e] = 0.f;

        #pragma unroll
        for (int kg = 0; kg < 16; kg++) {       // k-groups of 8
            const float* pa = xp + (mi * 16 + lr) * XPS + kg * 8 + lc * 2;
            float2 a0 = *(const float2*)pa;             // (A[r][k+lc], A[r][k+4+lc])
            float2 a1 = *(const float2*)(pa + 8 * XPS); // row +8
            unsigned af[4] = { fau(a0.x), fau(a1.x), fau(a0.y), fau(a1.y) };
            const float* wrow = g_wqkv_p + (kg * 4 + lc) * WQS;
            #pragma unroll
            for (int j = 0; j < 12; j++) {
                int n = nq * 96 + j * 8 + lr;
                float2 bw = *(const float2*)(wrow + n * 2);
                unsigned bf[2] = { fau(bw.x), fau(bw.y) };
                mma8(acc[j], af, bf);
            }
        }

        // scatter to qs / kTp / vsp (tf32-rounded)
        #pragma unroll
        for (int j = 0; j < 12; j++) {
            int colbase = nq * 96 + j * 8;
            int panel = colbase >> 7;
            int pc = colbase & 127;
            #pragma unroll
            for (int eh = 0; eh < 2; eh++) {
                int row = mi * 16 + lr + 8 * eh;
                #pragma unroll
                for (int e = 0; e < 2; e++) {
                    float val = acc[j][2 * eh + e];
                    int cc = pc + 2 * lc + e;
                    if (panel == 0) {
                        qs[row * QSS + (cc >> 3) * 8 + (cc & 3) * 2 + ((cc >> 2) & 1)]
                            = uaf(f2tf(val * SCALE));
                    } else if (panel == 1) {
                        kTp[((cc >> 3) * 4 + (cc & 3)) * KTS2 + row * 2 + ((cc >> 2) & 1)]
                            = uaf(f2tf(val));
                    } else {
                        vsp[((row >> 3) * 4 + (row & 3)) * VSS2 + cc * 2 + ((row >> 2) & 1)]
                            = uaf(f2tf(val));
                    }
                }
            }
        }
    }
    __syncthreads();

    // =================== Phase 2: S = Q K^T + bias ===================
    // 4 warps per head; warp owns 16 token-cols
    {
        const int h = wid >> 2, om = wid & 3;
        float acc[4][2][4];
        #pragma unroll
        for (int i = 0; i < 4; i++)
            #pragma unroll
            for (int j = 0; j < 2; j++)
                #pragma unroll
                for (int e = 0; e < 4; e++) acc[i][j][e] = 0.f;

        #pragma unroll
        for (int ks = 0; ks < 4; ks++) {
            int kk = h * 32 + ks * 8;
            int kg = kk >> 3;
            const float* krow = kTp + (kg * 4 + lc) * KTS2;
            unsigned bf[2][2];
            #pragma unroll
            for (int j = 0; j < 2; j++) {
                int n = om * 16 + j * 8 + lr;
                float2 kv = *(const float2*)(krow + n * 2);
                bf[j][0] = fau(kv.x); bf[j][1] = fau(kv.y);
            }
            #pragma unroll
            for (int i = 0; i < 4; i++) {
                const float* pq = qs + (i * 16 + lr) * QSS + kg * 8 + lc * 2;
                float2 q0 = *(const float2*)pq;
                float2 q1 = *(const float2*)(pq + 8 * QSS);
                unsigned af[4] = { fau(q0.x), fau(q1.x), fau(q0.y), fau(q1.y) };
                #pragma unroll
                for (int j = 0; j < 2; j++) mma8(acc[i][j], af, bf[j]);
            }
        }

        __syncthreads();   // qs/kTp reads complete: Ss aliases that memory

        float* Sh = Ss + h * (NTOK * SSS);
        const float* bh = g_bias + h * NTOK * NTOK;
        #pragma unroll
        for (int i = 0; i < 4; i++)
            #pragma unroll
            for (int j = 0; j < 2; j++) {
                int n0 = om * 16 + j * 8 + 2 * lc;
                #pragma unroll
                for (int eh = 0; eh < 2; eh++) {
                    int row = i * 16 + lr + 8 * eh;
                    float2 bv = *(const float2*)(bh + row * 64 + n0);
                    *(float2*)(Sh + row * SSS + n0) =
                        make_float2(acc[i][j][2 * eh] + bv.x,
                                    acc[i][j][2 * eh + 1] + bv.y);
                }
            }
    }
    __syncthreads();

    // =================== Phase 3: softmax (rounds P to tf32) ===================
    {
        int h = tid >> 7;
        int row = (tid >> 1) & 63;
        int half = tid & 1;
        float* sr = Ss + h * (NTOK * SSS) + row * SSS + half * 32;
        float v[32];
        float mx = -1e30f;
        #pragma unroll
        for (int j = 0; j < 32; j++) { v[j] = sr[j]; mx = fmaxf(mx, v[j]); }
        mx = fmaxf(mx, __shfl_xor_sync(0xffffffffu, mx, 1));
        float sum = 0.f;
        #pragma unroll
        for (int j = 0; j < 32; j++) { v[j] = __expf(v[j] - mx); sum += v[j]; }
        sum += __shfl_xor_sync(0xffffffffu, sum, 1);
        float inv = 1.0f / sum;
        #pragma unroll
        for (int j = 0; j < 32; j++) sr[j] = uaf(f2tf(v[j] * inv));
    }
    __syncthreads();

    // =================== Phase 4: O = P V, tf32 packed into xp ===================
    {
        const int h = wid >> 2, om = wid & 3;
        const float* Sh = Ss + h * (NTOK * SSS);
        float acc[4][4];
        #pragma unroll
        for (int i = 0; i < 4; i++)
            #pragma unroll
            for (int e = 0; e < 4; e++) acc[i][e] = 0.f;

        #pragma unroll
        for (int ks = 0; ks < 8; ks++) {
            int kk = ks * 8;
            int n = h * 32 + om * 8 + lr;
            float2 vv = *(const float2*)(vsp + (ks * 4 + lc) * VSS2 + n * 2);
            unsigned bf[2] = { fau(vv.x), fau(vv.y) };
            #pragma unroll
            for (int i = 0; i < 4; i++) {
                unsigned pf[4] = {
                    fau(Sh[(i * 16 + lr) * SSS + kk + lc]),
                    fau(Sh[(i * 16 + 8 + lr) * SSS + kk + lc]),
                    fau(Sh[(i * 16 + lr) * SSS + kk + 4 + lc]),
                    fau(Sh[(i * 16 + 8 + lr) * SSS + kk + 4 + lc]) };
                mma8(acc[i], pf, bf);
            }
        }

        #pragma unroll
        for (int i = 0; i < 4; i++)
            #pragma unroll
            for (int eh = 0; eh < 2; eh++) {
                int row = i * 16 + lr + 8 * eh;
                #pragma unroll
                for (int e = 0; e < 2; e++) {
                    int ch = h * 32 + om * 8 + 2 * lc + e;
                    xp[row * XPS + (ch >> 3) * 8 + (ch & 3) * 2 + ((ch >> 2) & 1)]
                        = uaf(f2tf(acc[i][2 * eh + e]));
                }
            }
    }
    __syncthreads();

    // =================== Phase 5: Y = tf32(O) @ tf32(Wproj) + b ===================
    // warp (mi, nq): m-tile mi, cols [nq*32, +32) = 4 n-tiles; B direct LDG
    {
        float acc[4][4];
        #pragma unroll
        for (int j = 0; j < 4; j++)
            #pragma unroll
            for (int e = 0; e < 4; e++) acc[j][e] = 0.f;

        #pragma unroll
        for (int kg = 0; kg < 16; kg++) {
            const float* pa = xp + (mi * 16 + lr) * XPS + kg * 8 + lc * 2;
            float2 a0 = *(const float2*)pa;
            float2 a1 = *(const float2*)(pa + 8 * XPS);
            unsigned af[4] = { fau(a0.x), fau(a1.x), fau(a0.y), fau(a1.y) };
            const float* wrow = g_wproj_p + (kg * 4 + lc) * WPS;
            #pragma unroll
            for (int j = 0; j < 4; j++) {
                int n = nq * 32 + j * 8 + lr;
                float2 bw = *(const float2*)(wrow + n * 2);
                unsigned bf[2] = { fau(bw.x), fau(bw.y) };
                mma8(acc[j], af, bf);
            }
        }

        float* ob = out + (size_t)b * NTOK * DIM;
        #pragma unroll
        for (int j = 0; j < 4; j++) {
            int c0 = nq * 32 + j * 8 + 2 * lc;
            float2 bb = *(const float2*)(bproj + c0);
            #pragma unroll
            for (int eh = 0; eh < 2; eh++) {
                int row = mi * 16 + lr + 8 * eh;
                *(float2*)(ob + row * DIM + c0) =
                    make_float2(acc[j][2 * eh] + bb.x, acc[j][2 * eh + 1] + bb.y);
            }
        }
    }
}

// ---------------------------------------------------------------------------
// Launch
// ---------------------------------------------------------------------------
extern "C" void kernel_launch(void* const* d_in, const int* in_sizes, int n_in,
                              void* d_out, int out_size)
{
    const float* x        = (const float*)d_in[0];
    const float* Wqkv     = (const float*)d_in[1];
    const float* Wproj    = (const float*)d_in[2];
    const float* bproj    = (const float*)d_in[3];
    const float* cpb_w1   = (const float*)d_in[4];
    const float* cpb_b1   = (const float*)d_in[5];
    const float* cpb_w2   = (const float*)d_in[6];
    const float* h_times  = (const float*)d_in[7];
    const float* pow_para = (const float*)d_in[8];
    const float* ws1      = (const float*)d_in[9];
    const float* ws2      = (const float*)d_in[10];
    const int*   rel_idx  = (const int*)d_in[11];
    const float* coords   = (const float*)d_in[12];

    int nwin = in_sizes[0] / (NTOK * DIM);

    int smem_bytes = SMEM_FLOATS * (int)sizeof(float);
    cudaFuncSetAttribute(attn_kernel,
                         cudaFuncAttributeMaxDynamicSharedMemorySize, smem_bytes);

    cpb_table_kernel<<<225, 128>>>(cpb_w1, cpb_b1, cpb_w2, h_times, pow_para,
                                   ws1, ws2, coords);
    bias_expand_kernel<<<16, 256>>>(rel_idx);
    pack_kernel<<<96, 256>>>(Wqkv, Wproj);
    attn_kernel<<<nwin, 512, smem_bytes>>>(x, bproj, (float*)d_out);
}

// round 6
// speedup vs baseline: 2.5355x; 1.0037x over previous
#include <cuda_runtime.h>
#include <math.h>

#define NTOK 64
#define DIM 128
#define NHEADS 4
#define SCALE 0.1767766952966369f   // 32^-0.5

// paired-layout strides (floats)
#define XS2 272          // xp2/qs2 rowslot stride: 16 kgroups*16 + 16 pad (shift 16 banks)
#define SRS 144          // Ss rowslot stride: 8 kgroups*16 + 16 pad
#define KTS 144          // kTp2 row stride: 4 npairs*32 + 16 pad
#define VSS2 264         // vsp row stride (unchanged)
#define WQ4S 768         // packed Wqkv row stride: 24 npairs*32 (exact)
#define WP4S 256         // packed Wproj row stride: 8 npairs*32 (exact)

#define OFF_XP 0                     // 32*272 = 8704   x -> later O
#define OFF_QS 8704                  // 32*272 = 8704
#define OFF_KT 17408                 // 64*144 = 9216
#define OFF_VS 26624                 // 32*264 = 8448
#define OFF_SS 35072                 // 4*32*144 = 18432
#define SMEM_FLOATS 53504            // 214,016 B

__device__ float g_table[225 * 4];
__device__ float g_bias[NHEADS * NTOK * NTOK];
__device__ float g_wqkv_p4[64 * WQ4S];
__device__ float g_wproj_p4[64 * WP4S];

__device__ __forceinline__ unsigned f2tf(float x) {
    unsigned r; asm("cvt.rna.tf32.f32 %0, %1;" : "=r"(r) : "f"(x)); return r;
}
__device__ __forceinline__ float uaf(unsigned x) { return __uint_as_float(x); }
__device__ __forceinline__ unsigned fau(float x) { return __float_as_uint(x); }

__device__ __forceinline__ void mma8(float* c, const unsigned* a, const unsigned* b) {
    asm volatile(
        "mma.sync.aligned.m16n8k8.row.col.f32.tf32.tf32.f32 "
        "{%0,%1,%2,%3}, {%4,%5,%6,%7}, {%8,%9}, {%0,%1,%2,%3};"
        : "+f"(c[0]), "+f"(c[1]), "+f"(c[2]), "+f"(c[3])
        : "r"(a[0]), "r"(a[1]), "r"(a[2]), "r"(a[3]), "r"(b[0]), "r"(b[1]));
}

// A-paired element index: float4 slot (rowslot, kgroup, k&3), component
// ((k>>2)&1)*2 + ((row>>3)&1). Slot holds (A[r][k], A[r+8][k], A[r][k+4], A[r+8][k+4]).
__device__ __forceinline__ int apack_idx(int row, int k, int stride) {
    int rs = ((row >> 4) << 3) + (row & 7);
    return rs * stride + ((k >> 3) << 4) + ((k & 3) << 2)
         + (((k >> 2) & 1) << 1) + ((row >> 3) & 1);
}
// B-paired element index (K^T / weights): row rb=(k>>3)*4+(k&3); slot holds
// (B[k][n], B[k+4][n], B[k][n+8], B[k+4][n+8]) at n = 16p + (n&7).
__device__ __forceinline__ int bpack_idx(int k, int n, int stride) {
    int rb = ((k >> 3) << 2) + (k & 3);
    return rb * stride + ((n >> 4) << 5) + ((n & 7) << 2)
         + (((n >> 3) & 1) << 1) + ((k >> 2) & 1);
}

// ---------------------------------------------------------------------------
// Setup A1: CPB table
// ---------------------------------------------------------------------------
__global__ void cpb_table_kernel(const float* __restrict__ cpb_w1,
                                 const float* __restrict__ cpb_b1,
                                 const float* __restrict__ cpb_w2,
                                 const float* __restrict__ h_times,
                                 const float* __restrict__ pow_para,
                                 const float* __restrict__ ws1,
                                 const float* __restrict__ ws2,
                                 const float* __restrict__ coords)
{
    __shared__ float red[128][4];
    const int t = blockIdx.x;
    const int tid = threadIdx.x;

    float ht = log1pf(expf(h_times[0]));
    float pp = 1.0f / (1.0f + expf(-pow_para[0]));
    float ws = log1pf(expf(ws1[0])) / log1pf(expf(ws2[0]));
    float t0 = coords[t * 2 + 0] * ht;
    float t1 = coords[t * 2 + 1] * ht;
    float s0 = (float)((t0 > 0.f) - (t0 < 0.f));
    float s1 = (float)((t1 > 0.f) - (t1 < 0.f));
    t0 = s0 * powf(fabsf(t0) + 1e-6f, pp) * ws;
    t1 = s1 * powf(fabsf(t1) + 1e-6f, pp) * ws;

    float a0 = 0.f, a1 = 0.f, a2 = 0.f, a3 = 0.f;
    for (int j = tid; j < 512; j += 128) {
        float hsum = fmaf(t0, cpb_w1[j], fmaf(t1, cpb_w1[512 + j], cpb_b1[j]));
        hsum = fmaxf(hsum, 0.f);
        a0 = fmaf(hsum, cpb_w2[j * 4 + 0], a0);
        a1 = fmaf(hsum, cpb_w2[j * 4 + 1], a1);
        a2 = fmaf(hsum, cpb_w2[j * 4 + 2], a2);
        a3 = fmaf(hsum, cpb_w2[j * 4 + 3], a3);
    }
    red[tid][0] = a0; red[tid][1] = a1; red[tid][2] = a2; red[tid][3] = a3;
    __syncthreads();
    for (int s = 64; s > 0; s >>= 1) {
        if (tid < s) {
            red[tid][0] += red[tid + s][0];
            red[tid][1] += red[tid + s][1];
            red[tid][2] += red[tid + s][2];
            red[tid][3] += red[tid + s][3];
        }
        __syncthreads();
    }
    if (tid < 4) g_table[t * 4 + tid] = red[0][tid];
}

// ---------------------------------------------------------------------------
// Setup A2: expand bias via rel_index (row-major [h][64][64])
// ---------------------------------------------------------------------------
__global__ void bias_expand_kernel(const int* __restrict__ rel_index)
{
    int ij = blockIdx.x * blockDim.x + threadIdx.x;
    if (ij < NTOK * NTOK) {
        int ri = rel_index[ij];
        #pragma unroll
        for (int h = 0; h < 4; h++)
            g_bias[h * NTOK * NTOK + ij] = g_table[ri * 4 + h];
    }
}

// ---------------------------------------------------------------------------
// Setup B: tf32-round + B-pair-pack weights
// ---------------------------------------------------------------------------
__global__ void pack_kernel(const float* __restrict__ Wqkv,
                            const float* __restrict__ Wproj)
{
    int tid = blockIdx.x * blockDim.x + threadIdx.x;
    int stride = gridDim.x * blockDim.x;
    for (int i = tid; i < 128 * 384; i += stride) {
        int k = i / 384, n = i % 384;
        g_wqkv_p4[bpack_idx(k, n, WQ4S)] = uaf(f2tf(Wqkv[(size_t)k * 384 + n]));
    }
    for (int i = tid; i < 128 * 128; i += stride) {
        int k = i / 128, n = i % 128;
        g_wproj_p4[bpack_idx(k, n, WP4S)] = uaf(f2tf(Wproj[(size_t)k * 128 + n]));
    }
}

// ---------------------------------------------------------------------------
// Main fused kernel: 1 window / CTA, 512 threads = 16 warps
// ---------------------------------------------------------------------------
__global__ void __launch_bounds__(512, 1)
attn_kernel(const float* __restrict__ x,
            const float* __restrict__ bproj,
            float*       __restrict__ out)
{
    extern __shared__ float sm[];
    float* xp2 = sm + OFF_XP;     // tf32 x (later O), A-paired
    float* qs2 = sm + OFF_QS;     // tf32 q*scale, A-paired
    float* kTp = sm + OFF_KT;     // tf32 k, B-paired
    float* vsp = sm + OFF_VS;     // tf32 v, B-fragment rows
    float* Ss  = sm + OFF_SS;     // scores, A-paired per head

    const int tid  = threadIdx.x;
    const int lane = tid & 31;
    const int wid  = tid >> 5;
    const int lr   = lane >> 2;   // 0..7
    const int lc   = lane & 3;    // 0..3
    const int b    = blockIdx.x;

    // ---- load x -> tf32, A-paired ----
    const float4* xb = (const float4*)(x + (size_t)b * NTOK * DIM);
    #pragma unroll
    for (int i = 0; i < 4; i++) {
        int f = tid + i * 512;
        float4 v = xb[f];
        int r = f >> 5, c0 = (f & 31) << 2;
        xp2[apack_idx(r, c0 + 0, XS2)] = uaf(f2tf(v.x));
        xp2[apack_idx(r, c0 + 1, XS2)] = uaf(f2tf(v.y));
        xp2[apack_idx(r, c0 + 2, XS2)] = uaf(f2tf(v.z));
        xp2[apack_idx(r, c0 + 3, XS2)] = uaf(f2tf(v.w));
    }
    __syncthreads();

    // =================== Phase 1: qkv = tf32(x) @ tf32(Wqkv) ===================
    // warp = (mi2 = wid&1 [m half], nq8 = wid>>1 [48-col slab = 3 n-pairs])
    {
        const int mi2 = wid & 1;
        const int nq8 = wid >> 1;
        float acc[2][6][4];
        #pragma unroll
        for (int m = 0; m < 2; m++)
            #pragma unroll
            for (int j = 0; j < 6; j++)
                #pragma unroll
                for (int e = 0; e < 4; e++) acc[m][j][e] = 0.f;

        #pragma unroll
        for (int kg = 0; kg < 16; kg++) {
            unsigned af[2][4];
            #pragma unroll
            for (int m = 0; m < 2; m++) {
                float4 av = *(const float4*)(xp2 + ((mi2 * 2 + m) * 8 + lr) * XS2
                                             + kg * 16 + lc * 4);
                af[m][0] = fau(av.x); af[m][1] = fau(av.y);
                af[m][2] = fau(av.z); af[m][3] = fau(av.w);
            }
            const float* wrow = g_wqkv_p4 + (kg * 4 + lc) * WQ4S;
            #pragma unroll
            for (int pp = 0; pp < 3; pp++) {
                float4 bv = *(const float4*)(wrow + ((nq8 * 3 + pp) * 8 + lr) * 4);
                unsigned b0[2] = { fau(bv.x), fau(bv.y) };
                unsigned b1[2] = { fau(bv.z), fau(bv.w) };
                #pragma unroll
                for (int m = 0; m < 2; m++) {
                    mma8(acc[m][2 * pp],     af[m], b0);
                    mma8(acc[m][2 * pp + 1], af[m], b1);
                }
            }
        }

        // scatter to qs2 / kTp / vsp (tf32-rounded)
        #pragma unroll
        for (int m = 0; m < 2; m++) {
            #pragma unroll
            for (int j = 0; j < 6; j++) {
                int colbase = nq8 * 48 + j * 8;
                int panel = colbase >> 7;
                #pragma unroll
                for (int eh = 0; eh < 2; eh++) {
                    int row = (mi2 * 2 + m) * 16 + lr + 8 * eh;
                    #pragma unroll
                    for (int e = 0; e < 2; e++) {
                        float val = acc[m][j][2 * eh + e];
                        int cc = (colbase & 127) + 2 * lc + e;
                        if (panel == 0) {
                            qs2[apack_idx(row, cc, XS2)] = uaf(f2tf(val * SCALE));
                        } else if (panel == 1) {
                            kTp[bpack_idx(cc, row, KTS)] = uaf(f2tf(val));
                        } else {
                            vsp[((row >> 3) * 4 + (row & 3)) * VSS2 + cc * 2
                                + ((row >> 2) & 1)] = uaf(f2tf(val));
                        }
                    }
                }
            }
        }
    }
    __syncthreads();

    // =================== Phase 2: S = Q K^T + bias ===================
    // 4 warps per head; warp owns n-pair om (16 token-cols), all 64 rows
    {
        const int h = wid >> 2, om = wid & 3;
        float acc[4][2][4];
        #pragma unroll
        for (int i = 0; i < 4; i++)
            #pragma unroll
            for (int j = 0; j < 2; j++)
                #pragma unroll
                for (int e = 0; e < 4; e++) acc[i][j][e] = 0.f;

        #pragma unroll
        for (int ks = 0; ks < 4; ks++) {
            int kg = h * 4 + ks;
            float4 kv = *(const float4*)(kTp + (kg * 4 + lc) * KTS + om * 32 + lr * 4);
            unsigned b0[2] = { fau(kv.x), fau(kv.y) };
            unsigned b1[2] = { fau(kv.z), fau(kv.w) };
            #pragma unroll
            for (int i = 0; i < 4; i++) {
                float4 qv = *(const float4*)(qs2 + (i * 8 + lr) * XS2 + kg * 16 + lc * 4);
                unsigned af[4] = { fau(qv.x), fau(qv.y), fau(qv.z), fau(qv.w) };
                mma8(acc[i][0], af, b0);
                mma8(acc[i][1], af, b1);
            }
        }

        float* Sh = Ss + h * (32 * SRS);
        const float* bh = g_bias + h * NTOK * NTOK;
        #pragma unroll
        for (int i = 0; i < 4; i++)
            #pragma unroll
            for (int j = 0; j < 2; j++)
                #pragma unroll
                for (int eh = 0; eh < 2; eh++) {
                    int row = i * 16 + lr + 8 * eh;
                    int c0 = om * 16 + j * 8 + 2 * lc;
                    float2 bv = *(const float2*)(bh + row * 64 + c0);
                    Sh[apack_idx(row, c0,     SRS)] = acc[i][j][2 * eh]     + bv.x;
                    Sh[apack_idx(row, c0 + 1, SRS)] = acc[i][j][2 * eh + 1] + bv.y;
                }
    }
    __syncthreads();

    // =================== Phase 3: softmax on paired layout ===================
    // thread quad handles one row-pair (rows r, r+8); quad member = k&3 class
    {
        int quad = tid & 3;
        int rp = tid >> 2;            // 0..127
        int h = rp >> 5, rs = rp & 31;
        float* Sh = Ss + h * (32 * SRS) + rs * SRS + quad * 4;
        float4 v[8];
        float mxA = -1e30f, mxB = -1e30f;
        #pragma unroll
        for (int g = 0; g < 8; g++) {
            v[g] = *(const float4*)(Sh + g * 16);
            mxA = fmaxf(mxA, fmaxf(v[g].x, v[g].z));
            mxB = fmaxf(mxB, fmaxf(v[g].y, v[g].w));
        }
        mxA = fmaxf(mxA, __shfl_xor_sync(0xffffffffu, mxA, 1));
        mxA = fmaxf(mxA, __shfl_xor_sync(0xffffffffu, mxA, 2));
        mxB = fmaxf(mxB, __shfl_xor_sync(0xffffffffu, mxB, 1));
        mxB = fmaxf(mxB, __shfl_xor_sync(0xffffffffu, mxB, 2));
        float sA = 0.f, sB = 0.f;
        #pragma unroll
        for (int g = 0; g < 8; g++) {
            v[g].x = __expf(v[g].x - mxA); sA += v[g].x;
            v[g].z = __expf(v[g].z - mxA); sA += v[g].z;
            v[g].y = __expf(v[g].y - mxB); sB += v[g].y;
            v[g].w = __expf(v[g].w - mxB); sB += v[g].w;
        }
        sA += __shfl_xor_sync(0xffffffffu, sA, 1);
        sA += __shfl_xor_sync(0xffffffffu, sA, 2);
        sB += __shfl_xor_sync(0xffffffffu, sB, 1);
        sB += __shfl_xor_sync(0xffffffffu, sB, 2);
        float iA = 1.0f / sA, iB = 1.0f / sB;
        #pragma unroll
        for (int g = 0; g < 8; g++) {
            float4 w;
            w.x = uaf(f2tf(v[g].x * iA));
            w.y = uaf(f2tf(v[g].y * iB));
            w.z = uaf(f2tf(v[g].z * iA));
            w.w = uaf(f2tf(v[g].w * iB));
            *(float4*)(Sh + g * 16) = w;
        }
    }
    __syncthreads();

    // =================== Phase 4: O = P V into xp2 (A-paired) ===================
    {
        const int h = wid >> 2, om = wid & 3;
        const float* Sh = Ss + h * (32 * SRS);
        const int n = h * 32 + om * 8 + lr;
        float acc[4][4];
        #pragma unroll
        for (int i = 0; i < 4; i++)
            #pragma unroll
            for (int e = 0; e < 4; e++) acc[i][e] = 0.f;

        #pragma unroll
        for (int ks = 0; ks < 8; ks++) {
            float2 vv = *(const float2*)(vsp + (ks * 4 + lc) * VSS2 + n * 2);
            unsigned bf[2] = { fau(vv.x), fau(vv.y) };
            #pragma unroll
            for (int i = 0; i < 4; i++) {
                float4 pv = *(const float4*)(Sh + (i * 8 + lr) * SRS + ks * 16 + lc * 4);
                unsigned af[4] = { fau(pv.x), fau(pv.y), fau(pv.z), fau(pv.w) };
                mma8(acc[i], af, bf);
            }
        }

        #pragma unroll
        for (int i = 0; i < 4; i++)
            #pragma unroll
            for (int eh = 0; eh < 2; eh++) {
                int row = i * 16 + lr + 8 * eh;
                #pragma unroll
                for (int e = 0; e < 2; e++) {
                    int ch = h * 32 + om * 8 + 2 * lc + e;
                    xp2[apack_idx(row, ch, XS2)] = uaf(f2tf(acc[i][2 * eh + e]));
                }
            }
    }
    __syncthreads();

    // =================== Phase 5: Y = tf32(O) @ tf32(Wproj) + b ===================
    // warp = (mi2 = wid&1, p8 = wid>>1 [n-pair, 16 cols])
    {
        const int mi2 = wid & 1;
        const int p8 = wid >> 1;
        float acc[2][2][4];
        #pragma unroll
        for (int m = 0; m < 2; m++)
            #pragma unroll
            for (int j = 0; j < 2; j++)
                #pragma unroll
                for (int e = 0; e < 4; e++) acc[m][j][e] = 0.f;

        #pragma unroll
        for (int kg = 0; kg < 16; kg++) {
            unsigned af[2][4];
            #pragma unroll
            for (int m = 0; m < 2; m++) {
                float4 av = *(const float4*)(xp2 + ((mi2 * 2 + m) * 8 + lr) * XS2
                                             + kg * 16 + lc * 4);
                af[m][0] = fau(av.x); af[m][1] = fau(av.y);
                af[m][2] = fau(av.z); af[m][3] = fau(av.w);
            }
            float4 bv = *(const float4*)(g_wproj_p4 + (kg * 4 + lc) * WP4S
                                         + (p8 * 8 + lr) * 4);
            unsigned b0[2] = { fau(bv.x), fau(bv.y) };
            unsigned b1[2] = { fau(bv.z), fau(bv.w) };
            #pragma unroll
            for (int m = 0; m < 2; m++) {
                mma8(acc[m][0], af[m], b0);
                mma8(acc[m][1], af[m], b1);
            }
        }

        float* ob = out + (size_t)b * NTOK * DIM;
        #pragma unroll
        for (int m = 0; m < 2; m++)
            #pragma unroll
            for (int j = 0; j < 2; j++) {
                int c0 = p8 * 16 + j * 8 + 2 * lc;
                float2 bb = *(const float2*)(bproj + c0);
                #pragma unroll
                for (int eh = 0; eh < 2; eh++) {
                    int row = (mi2 * 2 + m) * 16 + lr + 8 * eh;
                    *(float2*)(ob + row * DIM + c0) =
                        make_float2(acc[m][j][2 * eh] + bb.x,
                                    acc[m][j][2 * eh + 1] + bb.y);
                }
            }
    }
}

// ---------------------------------------------------------------------------
// Launch
// ---------------------------------------------------------------------------
extern "C" void kernel_launch(void* const* d_in, const int* in_sizes, int n_in,
                              void* d_out, int out_size)
{
    const float* x        = (const float*)d_in[0];
    const float* Wqkv     = (const float*)d_in[1];
    const float* Wproj    = (const float*)d_in[2];
    const float* bproj    = (const float*)d_in[3];
    const float* cpb_w1   = (const float*)d_in[4];
    const float* cpb_b1   = (const float*)d_in[5];
    const float* cpb_w2   = (const float*)d_in[6];
    const float* h_times  = (const float*)d_in[7];
    const float* pow_para = (const float*)d_in[8];
    const float* ws1      = (const float*)d_in[9];
    const float* ws2      = (const float*)d_in[10];
    const int*   rel_idx  = (const int*)d_in[11];
    const float* coords   = (const float*)d_in[12];

    int nwin = in_sizes[0] / (NTOK * DIM);

    int smem_bytes = SMEM_FLOATS * (int)sizeof(float);
    cudaFuncSetAttribute(attn_kernel,
                         cudaFuncAttributeMaxDynamicSharedMemorySize, smem_bytes);

    cpb_table_kernel<<<225, 128>>>(cpb_w1, cpb_b1, cpb_w2, h_times, pow_para,
                                   ws1, ws2, coords);
    bias_expand_kernel<<<16, 256>>>(rel_idx);
    pack_kernel<<<192, 256>>>(Wqkv, Wproj);
    attn_kernel<<<nwin, 512, smem_bytes>>>(x, bproj, (float*)d_out);
}

// round 7
// speedup vs baseline: 3.7808x; 1.4911x over previous
#include <cuda_runtime.h>
#include <math.h>

#define NTOK 64
#define DIM 128
#define NHEADS 4
#define SCALE 0.1767766952966369f   // 32^-0.5

#define XS2 272          // xp2 rowslot stride (x / O, A-paired)
#define KTS 136          // kTp row stride (conflict-free: 136 % 32 = 8)
#define VSS2 264         // vsp row stride
#define WQ4S 768         // packed Wqkv row stride
#define WP4S 256         // packed Wproj row stride

#define OFF_KT 8704
#define OFF_VS 17408
#define SMEM_FLOATS 25856            // 103,424 B -> 2 CTAs / SM

__device__ float g_table[225 * 4];
__device__ float g_bias[NHEADS * NTOK * NTOK];
__device__ float g_wqkv_p4[64 * WQ4S];
__device__ float g_wproj_p4[64 * WP4S];

__device__ __forceinline__ unsigned f2tf(float x) {
    unsigned r; asm("cvt.rna.tf32.f32 %0, %1;" : "=r"(r) : "f"(x)); return r;
}
__device__ __forceinline__ float uaf(unsigned x) { return __uint_as_float(x); }
__device__ __forceinline__ unsigned fau(float x) { return __float_as_uint(x); }

__device__ __forceinline__ void mma8(float* c, const unsigned* a, const unsigned* b) {
    asm volatile(
        "mma.sync.aligned.m16n8k8.row.col.f32.tf32.tf32.f32 "
        "{%0,%1,%2,%3}, {%4,%5,%6,%7}, {%8,%9}, {%0,%1,%2,%3};"
        : "+f"(c[0]), "+f"(c[1]), "+f"(c[2]), "+f"(c[3])
        : "r"(a[0]), "r"(a[1]), "r"(a[2]), "r"(a[3]), "r"(b[0]), "r"(b[1]));
}

// A-paired: slot(rowslot, kgroup, k&3); comps ((k>>2)&1)*2 + ((row>>3)&1)
__device__ __forceinline__ int apack_idx(int row, int k, int stride) {
    int rs = ((row >> 4) << 3) + (row & 7);
    return rs * stride + ((k >> 3) << 4) + ((k & 3) << 2)
         + (((k >> 2) & 1) << 1) + ((row >> 3) & 1);
}
// B-paired: row rb=(k>>3)*4+(k&3); slot holds (B[k][n],B[k+4][n],B[k][n+8],B[k+4][n+8])
__device__ __forceinline__ int bpack_idx(int k, int n, int stride) {
    int rb = ((k >> 3) << 2) + (k & 3);
    return rb * stride + ((n >> 4) << 5) + ((n & 7) << 2)
         + (((n >> 3) & 1) << 1) + ((k >> 2) & 1);
}

// C-layout fragment (4 regs: rows lr/lr+8 at cols 2lc,2lc+1 of one 8-col group)
// -> A-fragment for the same 8-col group as k-dim. Pure quad shuffles.
__device__ __forceinline__ void c2a(const float* c4, int s0, int s1, int odd,
                                    unsigned* af) {
    float x0 = __shfl_sync(0xffffffffu, c4[0], s0);
    float x1 = __shfl_sync(0xffffffffu, c4[1], s0);
    float y0 = __shfl_sync(0xffffffffu, c4[2], s0);
    float y1 = __shfl_sync(0xffffffffu, c4[3], s0);
    float z0 = __shfl_sync(0xffffffffu, c4[0], s1);
    float z1 = __shfl_sync(0xffffffffu, c4[1], s1);
    float w0 = __shfl_sync(0xffffffffu, c4[2], s1);
    float w1 = __shfl_sync(0xffffffffu, c4[3], s1);
    af[0] = fau(odd ? x1 : x0);
    af[1] = fau(odd ? y1 : y0);
    af[2] = fau(odd ? z1 : z0);
    af[3] = fau(odd ? w1 : w0);
}

// ---------------------------------------------------------------------------
// Setup A1: CPB table
// ---------------------------------------------------------------------------
__global__ void cpb_table_kernel(const float* __restrict__ cpb_w1,
                                 const float* __restrict__ cpb_b1,
                                 const float* __restrict__ cpb_w2,
                                 const float* __restrict__ h_times,
                                 const float* __restrict__ pow_para,
                                 const float* __restrict__ ws1,
                                 const float* __restrict__ ws2,
                                 const float* __restrict__ coords)
{
    __shared__ float red[128][4];
    const int t = blockIdx.x;
    const int tid = threadIdx.x;

    float ht = log1pf(expf(h_times[0]));
    float pp = 1.0f / (1.0f + expf(-pow_para[0]));
    float ws = log1pf(expf(ws1[0])) / log1pf(expf(ws2[0]));
    float t0 = coords[t * 2 + 0] * ht;
    float t1 = coords[t * 2 + 1] * ht;
    float s0 = (float)((t0 > 0.f) - (t0 < 0.f));
    float s1 = (float)((t1 > 0.f) - (t1 < 0.f));
    t0 = s0 * powf(fabsf(t0) + 1e-6f, pp) * ws;
    t1 = s1 * powf(fabsf(t1) + 1e-6f, pp) * ws;

    float a0 = 0.f, a1 = 0.f, a2 = 0.f, a3 = 0.f;
    for (int j = tid; j < 512; j += 128) {
        float hsum = fmaf(t0, cpb_w1[j], fmaf(t1, cpb_w1[512 + j], cpb_b1[j]));
        hsum = fmaxf(hsum, 0.f);
        a0 = fmaf(hsum, cpb_w2[j * 4 + 0], a0);
        a1 = fmaf(hsum, cpb_w2[j * 4 + 1], a1);
        a2 = fmaf(hsum, cpb_w2[j * 4 + 2], a2);
        a3 = fmaf(hsum, cpb_w2[j * 4 + 3], a3);
    }
    red[tid][0] = a0; red[tid][1] = a1; red[tid][2] = a2; red[tid][3] = a3;
    __syncthreads();
    for (int s = 64; s > 0; s >>= 1) {
        if (tid < s) {
            red[tid][0] += red[tid + s][0];
            red[tid][1] += red[tid + s][1];
            red[tid][2] += red[tid + s][2];
            red[tid][3] += red[tid + s][3];
        }
        __syncthreads();
    }
    if (tid < 4) g_table[t * 4 + tid] = red[0][tid];
}

__global__ void bias_expand_kernel(const int* __restrict__ rel_index)
{
    int ij = blockIdx.x * blockDim.x + threadIdx.x;
    if (ij < NTOK * NTOK) {
        int ri = rel_index[ij];
        #pragma unroll
        for (int h = 0; h < 4; h++)
            g_bias[h * NTOK * NTOK + ij] = g_table[ri * 4 + h];
    }
}

__global__ void pack_kernel(const float* __restrict__ Wqkv,
                            const float* __restrict__ Wproj)
{
    int tid = blockIdx.x * blockDim.x + threadIdx.x;
    int stride = gridDim.x * blockDim.x;
    for (int i = tid; i < 128 * 384; i += stride) {
        int k = i / 384, n = i % 384;
        g_wqkv_p4[bpack_idx(k, n, WQ4S)] = uaf(f2tf(Wqkv[(size_t)k * 384 + n]));
    }
    for (int i = tid; i < 128 * 128; i += stride) {
        int k = i / 128, n = i % 128;
        g_wproj_p4[bpack_idx(k, n, WP4S)] = uaf(f2tf(Wproj[(size_t)k * 128 + n]));
    }
}

// ---------------------------------------------------------------------------
// Main fused kernel: 1 window / CTA, 256 threads = 8 warps, 2 CTAs / SM
// warp wid: head h = wid>>1, row-half mh = wid&1 (rows mh*32..+32) for attn;
// kv producer slab = cols wid*32 of the kv panel; proj slab = cols wid*16.
// ---------------------------------------------------------------------------
__global__ void __launch_bounds__(256, 2)
attn_kernel(const float* __restrict__ x,
            const float* __restrict__ bproj,
            float*       __restrict__ out)
{
    extern __shared__ float sm[];
    float* xp2 = sm;              // tf32 x (later O), A-paired
    float* kTp = sm + OFF_KT;     // tf32 k, B-paired [channel][token]
    float* vsp = sm + OFF_VS;     // tf32 v, B-fragment rows [token][channel]

    const int tid  = threadIdx.x;
    const int lane = tid & 31;
    const int wid  = tid >> 5;    // 0..7
    const int lr   = lane >> 2;
    const int lc   = lane & 3;
    const int b    = blockIdx.x;
    const int h    = wid >> 1;
    const int mh   = wid & 1;

    // ---- load x -> tf32, A-paired ----
    const float4* xb = (const float4*)(x + (size_t)b * NTOK * DIM);
    #pragma unroll
    for (int i = 0; i < 8; i++) {
        int f = tid + i * 256;
        float4 v = xb[f];
        int r = f >> 5, c0 = (f & 31) << 2;
        xp2[apack_idx(r, c0 + 0, XS2)] = uaf(f2tf(v.x));
        xp2[apack_idx(r, c0 + 1, XS2)] = uaf(f2tf(v.y));
        xp2[apack_idx(r, c0 + 2, XS2)] = uaf(f2tf(v.z));
        xp2[apack_idx(r, c0 + 3, XS2)] = uaf(f2tf(v.w));
    }
    __syncthreads();

    // =================== Phase 1a: k/v slab (32 cols, all 64 rows) ===========
    {
        const int npbase = 8 + wid * 2;      // n-pair base in packed Wqkv (col 128 + wid*32)
        float kacc[4][4][4];
        #pragma unroll
        for (int mt = 0; mt < 4; mt++)
            #pragma unroll
            for (int nt = 0; nt < 4; nt++)
                #pragma unroll
                for (int e = 0; e < 4; e++) kacc[mt][nt][e] = 0.f;

        #pragma unroll
        for (int kg = 0; kg < 16; kg++) {
            unsigned af[4][4];
            #pragma unroll
            for (int mt = 0; mt < 4; mt++) {
                float4 av = *(const float4*)(xp2 + (mt * 8 + lr) * XS2 + kg * 16 + lc * 4);
                af[mt][0] = fau(av.x); af[mt][1] = fau(av.y);
                af[mt][2] = fau(av.z); af[mt][3] = fau(av.w);
            }
            const float* wrow = g_wqkv_p4 + (kg * 4 + lc) * WQ4S;
            #pragma unroll
            for (int np = 0; np < 2; np++) {
                float4 bv = *(const float4*)(wrow + ((npbase + np) * 8 + lr) * 4);
                unsigned b0[2] = { fau(bv.x), fau(bv.y) };
                unsigned b1[2] = { fau(bv.z), fau(bv.w) };
                #pragma unroll
                for (int mt = 0; mt < 4; mt++) {
                    mma8(kacc[mt][np * 2],     af[mt], b0);
                    mma8(kacc[mt][np * 2 + 1], af[mt], b1);
                }
            }
        }

        if (wid < 4) {
            // K slab: channels wid*32..+32
            #pragma unroll
            for (int mt = 0; mt < 4; mt++)
                #pragma unroll
                for (int nt = 0; nt < 4; nt++)
                    #pragma unroll
                    for (int eh = 0; eh < 2; eh++)
                        #pragma unroll
                        for (int e = 0; e < 2; e++) {
                            int row = mt * 16 + lr + 8 * eh;
                            int ch = wid * 32 + nt * 8 + 2 * lc + e;
                            kTp[bpack_idx(ch, row, KTS)] =
                                uaf(f2tf(kacc[mt][nt][2 * eh + e]));
                        }
        } else {
            // V slab: channels (wid-4)*32..+32
            #pragma unroll
            for (int mt = 0; mt < 4; mt++)
                #pragma unroll
                for (int nt = 0; nt < 4; nt++)
                    #pragma unroll
                    for (int eh = 0; eh < 2; eh++)
                        #pragma unroll
                        for (int e = 0; e < 2; e++) {
                            int row = mt * 16 + lr + 8 * eh;
                            int ch = (wid - 4) * 32 + nt * 8 + 2 * lc + e;
                            vsp[((row >> 3) * 4 + (row & 3)) * VSS2 + ch * 2
                                + ((row >> 2) & 1)] = uaf(f2tf(kacc[mt][nt][2 * eh + e]));
                        }
        }
    }

    // =================== Phase 1b: q tile (rows mh*32..+32, head-h cols) =====
    float qc[2][4][4];
    {
        #pragma unroll
        for (int mt = 0; mt < 2; mt++)
            #pragma unroll
            for (int nt = 0; nt < 4; nt++)
                #pragma unroll
                for (int e = 0; e < 4; e++) qc[mt][nt][e] = 0.f;

        #pragma unroll
        for (int kg = 0; kg < 16; kg++) {
            unsigned af[2][4];
            #pragma unroll
            for (int mt = 0; mt < 2; mt++) {
                float4 av = *(const float4*)(xp2 + ((mh * 2 + mt) * 8 + lr) * XS2
                                             + kg * 16 + lc * 4);
                af[mt][0] = fau(av.x); af[mt][1] = fau(av.y);
                af[mt][2] = fau(av.z); af[mt][3] = fau(av.w);
            }
            const float* wrow = g_wqkv_p4 + (kg * 4 + lc) * WQ4S;
            #pragma unroll
            for (int np = 0; np < 2; np++) {
                float4 bv = *(const float4*)(wrow + ((h * 2 + np) * 8 + lr) * 4);
                unsigned b0[2] = { fau(bv.x), fau(bv.y) };
                unsigned b1[2] = { fau(bv.z), fau(bv.w) };
                #pragma unroll
                for (int mt = 0; mt < 2; mt++) {
                    mma8(qc[mt][np * 2],     af[mt], b0);
                    mma8(qc[mt][np * 2 + 1], af[mt], b1);
                }
            }
        }
        // round + scale in registers
        #pragma unroll
        for (int mt = 0; mt < 2; mt++)
            #pragma unroll
            for (int nt = 0; nt < 4; nt++)
                #pragma unroll
                for (int e = 0; e < 4; e++)
                    qc[mt][nt][e] = uaf(f2tf(qc[mt][nt][e] * SCALE));
    }
    __syncthreads();

    // =================== Phases 2-4 fused in registers =======================
    const int s0 = lr * 4 + (lc >> 1), s1 = s0 + 2;
    const int odd = lc & 1;
    const float* bh = g_bias + h * NTOK * NTOK;

    #pragma unroll
    for (int mt = 0; mt < 2; mt++) {
        const int Rm = mh * 32 + mt * 16;

        // q C-layout -> A-fragments (quad shuffles, no smem)
        unsigned aq[4][4];
        #pragma unroll
        for (int kg = 0; kg < 4; kg++) c2a(qc[mt][kg], s0, s1, odd, aq[kg]);

        // S = Q K^T  (16 rows x 64 cols, K = head dims)
        float sacc[8][4];
        #pragma unroll
        for (int nt = 0; nt < 8; nt++)
            #pragma unroll
            for (int e = 0; e < 4; e++) sacc[nt][e] = 0.f;

        #pragma unroll
        for (int kg = 0; kg < 4; kg++) {
            const float* krow = kTp + ((h * 4 + kg) * 4 + lc) * KTS;
            #pragma unroll
            for (int np = 0; np < 4; np++) {
                float4 kv4 = *(const float4*)(krow + np * 32 + lr * 4);
                unsigned b0[2] = { fau(kv4.x), fau(kv4.y) };
                unsigned b1[2] = { fau(kv4.z), fau(kv4.w) };
                mma8(sacc[2 * np],     aq[kg], b0);
                mma8(sacc[2 * np + 1], aq[kg], b1);
            }
        }

        // bias + softmax in registers (rows Rm+lr, Rm+lr+8)
        const int r0 = Rm + lr, r1 = r0 + 8;
        float mx0 = -1e30f, mx1 = -1e30f;
        #pragma unroll
        for (int nt = 0; nt < 8; nt++) {
            float2 b0v = *(const float2*)(bh + r0 * 64 + nt * 8 + 2 * lc);
            float2 b1v = *(const float2*)(bh + r1 * 64 + nt * 8 + 2 * lc);
            sacc[nt][0] += b0v.x; sacc[nt][1] += b0v.y;
            sacc[nt][2] += b1v.x; sacc[nt][3] += b1v.y;
            mx0 = fmaxf(mx0, fmaxf(sacc[nt][0], sacc[nt][1]));
            mx1 = fmaxf(mx1, fmaxf(sacc[nt][2], sacc[nt][3]));
        }
        mx0 = fmaxf(mx0, __shfl_xor_sync(0xffffffffu, mx0, 1));
        mx0 = fmaxf(mx0, __shfl_xor_sync(0xffffffffu, mx0, 2));
        mx1 = fmaxf(mx1, __shfl_xor_sync(0xffffffffu, mx1, 1));
        mx1 = fmaxf(mx1, __shfl_xor_sync(0xffffffffu, mx1, 2));
        float sum0 = 0.f, sum1 = 0.f;
        #pragma unroll
        for (int nt = 0; nt < 8; nt++) {
            sacc[nt][0] = __expf(sacc[nt][0] - mx0); sum0 += sacc[nt][0];
            sacc[nt][1] = __expf(sacc[nt][1] - mx0); sum0 += sacc[nt][1];
            sacc[nt][2] = __expf(sacc[nt][2] - mx1); sum1 += sacc[nt][2];
            sacc[nt][3] = __expf(sacc[nt][3] - mx1); sum1 += sacc[nt][3];
        }
        sum0 += __shfl_xor_sync(0xffffffffu, sum0, 1);
        sum0 += __shfl_xor_sync(0xffffffffu, sum0, 2);
        sum1 += __shfl_xor_sync(0xffffffffu, sum1, 1);
        sum1 += __shfl_xor_sync(0xffffffffu, sum1, 2);
        const float i0 = 1.0f / sum0, i1 = 1.0f / sum1;
        #pragma unroll
        for (int nt = 0; nt < 8; nt++) {
            sacc[nt][0] = uaf(f2tf(sacc[nt][0] * i0));
            sacc[nt][1] = uaf(f2tf(sacc[nt][1] * i0));
            sacc[nt][2] = uaf(f2tf(sacc[nt][2] * i1));
            sacc[nt][3] = uaf(f2tf(sacc[nt][3] * i1));
        }

        // O = P V (P A-fragments via quad shuffles)
        float oacc[4][4];
        #pragma unroll
        for (int nt2 = 0; nt2 < 4; nt2++)
            #pragma unroll
            for (int e = 0; e < 4; e++) oacc[nt2][e] = 0.f;

        #pragma unroll
        for (int kg = 0; kg < 8; kg++) {
            unsigned ap[4];
            c2a(sacc[kg], s0, s1, odd, ap);
            const float* vrow = vsp + (kg * 4 + lc) * VSS2;
            #pragma unroll
            for (int nt2 = 0; nt2 < 4; nt2++) {
                float2 vv = *(const float2*)(vrow + (h * 32 + nt2 * 8 + lr) * 2);
                unsigned bf[2] = { fau(vv.x), fau(vv.y) };
                mma8(oacc[nt2], ap, bf);
            }
        }

        // scatter O (tf32) into xp2 (x is dead)
        #pragma unroll
        for (int nt2 = 0; nt2 < 4; nt2++)
            #pragma unroll
            for (int eh = 0; eh < 2; eh++)
                #pragma unroll
                for (int e = 0; e < 2; e++) {
                    int row = Rm + lr + 8 * eh;
                    int ch = h * 32 + nt2 * 8 + 2 * lc + e;
                    xp2[apack_idx(row, ch, XS2)] =
                        uaf(f2tf(oacc[nt2][2 * eh + e]));
                }
    }
    __syncthreads();

    // =================== Phase 5: Y = tf32(O) @ tf32(Wproj) + b ===============
    // warp wid: 16-col slab, all 4 m-tiles (B redundancy 1x)
    {
        float acc[4][2][4];
        #pragma unroll
        for (int mt = 0; mt < 4; mt++)
            #pragma unroll
            for (int j = 0; j < 2; j++)
                #pragma unroll
                for (int e = 0; e < 4; e++) acc[mt][j][e] = 0.f;

        #pragma unroll
        for (int kg = 0; kg < 16; kg++) {
            float4 bv = *(const float4*)(g_wproj_p4 + (kg * 4 + lc) * WP4S
                                         + (wid * 8 + lr) * 4);
            unsigned b0[2] = { fau(bv.x), fau(bv.y) };
            unsigned b1[2] = { fau(bv.z), fau(bv.w) };
            #pragma unroll
            for (int mt = 0; mt < 4; mt++) {
                float4 av = *(const float4*)(xp2 + (mt * 8 + lr) * XS2 + kg * 16 + lc * 4);
                unsigned af[4] = { fau(av.x), fau(av.y), fau(av.z), fau(av.w) };
                mma8(acc[mt][0], af, b0);
                mma8(acc[mt][1], af, b1);
            }
        }

        float* obp = out + (size_t)b * NTOK * DIM;
        #pragma unroll
        for (int mt = 0; mt < 4; mt++)
            #pragma unroll
            for (int j = 0; j < 2; j++) {
                int c0 = wid * 16 + j * 8 + 2 * lc;
                float2 bb = *(const float2*)(bproj + c0);
                #pragma unroll
                for (int eh = 0; eh < 2; eh++) {
                    int row = mt * 16 + lr + 8 * eh;
                    *(float2*)(obp + row * DIM + c0) =
                        make_float2(acc[mt][j][2 * eh] + bb.x,
                                    acc[mt][j][2 * eh + 1] + bb.y);
                }
            }
    }
}

// ---------------------------------------------------------------------------
// Launch
// ---------------------------------------------------------------------------
extern "C" void kernel_launch(void* const* d_in, const int* in_sizes, int n_in,
                              void* d_out, int out_size)
{
    const float* x        = (const float*)d_in[0];
    const float* Wqkv     = (const float*)d_in[1];
    const float* Wproj    = (const float*)d_in[2];
    const float* bproj    = (const float*)d_in[3];
    const float* cpb_w1   = (const float*)d_in[4];
    const float* cpb_b1   = (const float*)d_in[5];
    const float* cpb_w2   = (const float*)d_in[6];
    const float* h_times  = (const float*)d_in[7];
    const float* pow_para = (const float*)d_in[8];
    const float* ws1      = (const float*)d_in[9];
    const float* ws2      = (const float*)d_in[10];
    const int*   rel_idx  = (const int*)d_in[11];
    const float* coords   = (const float*)d_in[12];

    int nwin = in_sizes[0] / (NTOK * DIM);

    int smem_bytes = SMEM_FLOATS * (int)sizeof(float);
    cudaFuncSetAttribute(attn_kernel,
                         cudaFuncAttributeMaxDynamicSharedMemorySize, smem_bytes);

    cpb_table_kernel<<<225, 128>>>(cpb_w1, cpb_b1, cpb_w2, h_times, pow_para,
                                   ws1, ws2, coords);
    bias_expand_kernel<<<16, 256>>>(rel_idx);
    pack_kernel<<<192, 256>>>(Wqkv, Wproj);
    attn_kernel<<<nwin, 256, smem_bytes>>>(x, bproj, (float*)d_out);
}